// round 1
// baseline (speedup 1.0000x reference)
#include <cuda_runtime.h>

#define BATCH 1024
#define TT    133
#define TP    136            // padded T
#define DD    256
#define EE    512
#define SS    128
#define NUV   1152           // 2*E + S
#define MTOT  (BATCH*TT)     // 136192
#define INV_SQRT_S 0.08838834764831845f
#define EPSV  1e-5f

typedef unsigned long long ull;

// ---------------- scratch (static device globals; no runtime allocation) ----
__device__ float g_rn[MTOT];                         // per-row norm scale
__device__ float g_uv[(size_t)MTOT * NUV];           // silu(xn @ W_uv^T)  (627 MB)
__device__ float g_h [(size_t)MTOT * EE];            // u * attn           (279 MB)

// ---------------- packed fp32x2 helpers (sm_103a FFMA2 path) ----------------
__device__ __forceinline__ ull pk2(float x, float y) {
    ull r; asm("mov.b64 %0, {%1, %2};" : "=l"(r) : "f"(x), "f"(y)); return r;
}
__device__ __forceinline__ void upk(ull v, float &x, float &y) {
    asm("mov.b64 {%0, %1}, %2;" : "=f"(x), "=f"(y) : "l"(v));
}
__device__ __forceinline__ void fma2(ull &d, ull a, ull b) {
    asm("fma.rn.f32x2 %0, %1, %2, %0;" : "+l"(d) : "l"(a), "l"(b));
}

// 8x8 micro-tile update: rows from (a0,a1), cols from (b0,b1); acc packed by
// column pairs: acc[r][cp] holds cols (2cp, 2cp+1) of the 8-col micro-tile.
__device__ __forceinline__ void mstep(ull (&acc)[8][4],
                                      float4 a0, float4 a1,
                                      float4 b0, float4 b1) {
    ull bp[4];
    bp[0] = pk2(b0.x, b0.y); bp[1] = pk2(b0.z, b0.w);
    bp[2] = pk2(b1.x, b1.y); bp[3] = pk2(b1.z, b1.w);
    float av[8] = {a0.x, a0.y, a0.z, a0.w, a1.x, a1.y, a1.z, a1.w};
#pragma unroll
    for (int r = 0; r < 8; r++) {
        ull ad = pk2(av[r], av[r]);
#pragma unroll
        for (int c = 0; c < 4; c++) fma2(acc[r][c], ad, bp[c]);
    }
}

__device__ __forceinline__ float silu_f(float v) {
    return v / (1.0f + __expf(-v));
}

// ---------------- kernel 0: row norm scale --------------------------------
__global__ void k_rnorm(const float* __restrict__ x, const float* __restrict__ g) {
    int row = blockIdx.x * 8 + threadIdx.y;
    if (row >= MTOT) return;
    const float4* xr = (const float4*)(x + (size_t)row * DD);
    float s = 0.f;
#pragma unroll
    for (int i = threadIdx.x; i < 64; i += 32) {
        float4 v = xr[i];
        s += v.x*v.x + v.y*v.y + v.z*v.z + v.w*v.w;
    }
#pragma unroll
    for (int o = 16; o; o >>= 1) s += __shfl_xor_sync(0xffffffffu, s, o);
    if (threadIdx.x == 0) {
        float norm = sqrtf(s) * 0.0625f;          // / sqrt(256)
        g_rn[row] = g[0] / fmaxf(norm, EPSV);
    }
}

// ---------------- kernel 1: uv = silu( (rn*x) @ W_uv^T ) --------------------
// M=136192 (exactly 1064 tiles of 128), N=1152 (9 tiles), K=256. BK=16.
__global__ __launch_bounds__(256, 2)
void k_gemm_uv(const float* __restrict__ x, const float* __restrict__ W) {
    __shared__ float As[16][128];
    __shared__ float Bs[16][128];
    int tid = threadIdx.x;
    int m0 = blockIdx.x * 128, n0 = blockIdx.y * 128;
    int lr = tid >> 2;              // 0..63
    int lc = (tid & 3) * 4;         // 0,4,8,12
    const float* gA0 = x + (size_t)(m0 + lr)      * DD + lc;
    const float* gA1 = x + (size_t)(m0 + lr + 64) * DD + lc;
    const float* gB0 = W + (size_t)(n0 + lr)      * DD + lc;
    const float* gB1 = W + (size_t)(n0 + lr + 64) * DD + lc;
    float s0 = g_rn[m0 + lr], s1 = g_rn[m0 + lr + 64];
    int ty = tid >> 4, tx = tid & 15;

    ull acc[8][4];
#pragma unroll
    for (int r = 0; r < 8; r++)
#pragma unroll
        for (int c = 0; c < 4; c++) acc[r][c] = 0ull;

    for (int kt = 0; kt < DD; kt += 16) {
        float4 a0 = *(const float4*)(gA0 + kt);
        float4 a1 = *(const float4*)(gA1 + kt);
        float4 b0 = *(const float4*)(gB0 + kt);
        float4 b1 = *(const float4*)(gB1 + kt);
        __syncthreads();
        As[lc+0][lr] = a0.x*s0; As[lc+1][lr] = a0.y*s0;
        As[lc+2][lr] = a0.z*s0; As[lc+3][lr] = a0.w*s0;
        As[lc+0][lr+64] = a1.x*s1; As[lc+1][lr+64] = a1.y*s1;
        As[lc+2][lr+64] = a1.z*s1; As[lc+3][lr+64] = a1.w*s1;
        Bs[lc+0][lr] = b0.x; Bs[lc+1][lr] = b0.y;
        Bs[lc+2][lr] = b0.z; Bs[lc+3][lr] = b0.w;
        Bs[lc+0][lr+64] = b1.x; Bs[lc+1][lr+64] = b1.y;
        Bs[lc+2][lr+64] = b1.z; Bs[lc+3][lr+64] = b1.w;
        __syncthreads();
#pragma unroll
        for (int k = 0; k < 16; k++) {
            float4 ra0 = *(const float4*)&As[k][ty*4];
            float4 ra1 = *(const float4*)&As[k][64 + ty*4];
            float4 rb0 = *(const float4*)&Bs[k][tx*4];
            float4 rb1 = *(const float4*)&Bs[k][64 + tx*4];
            mstep(acc, ra0, ra1, rb0, rb1);
        }
    }
#pragma unroll
    for (int r = 0; r < 8; r++) {
        int m = m0 + ((r < 4) ? (ty*4 + r) : (64 + ty*4 + r - 4));
        float v0, v1, v2, v3;
        upk(acc[r][0], v0, v1); upk(acc[r][1], v2, v3);
        float4 o = make_float4(silu_f(v0), silu_f(v1), silu_f(v2), silu_f(v3));
        *(float4*)(g_uv + (size_t)m * NUV + n0 + tx*4) = o;
        upk(acc[r][2], v0, v1); upk(acc[r][3], v2, v3);
        o = make_float4(silu_f(v0), silu_f(v1), silu_f(v2), silu_f(v3));
        *(float4*)(g_uv + (size_t)m * NUV + n0 + 64 + tx*4) = o;
    }
}

// ---------------- kernel 2: per-batch attention -----------------------------
// smem: KerT[136][140] | QT[128][136] | KT[128][136]  (V chunk reuses QT/KT)
#define SM_KERT 0
#define SM_QT   (136*140)
#define SM_KT   (SM_QT + 128*136)
#define SM_FLOATS (SM_KT + 128*136)          // 53856 floats = 215424 B

__global__ __launch_bounds__(288, 1)
void k_attn(const float* __restrict__ gamma, const float* __restrict__ beta) {
    extern __shared__ float sm[];
    float* sKerT = sm + SM_KERT;     // [j][i] stride 140
    float* sQT   = sm + SM_QT;       // [s][i] stride 136
    float* sKT   = sm + SM_KT;
    float* sV    = sQT;              // [j][e] stride 132 (reuse)
    float* sBase = sKerT;            // [i][s] stride 132 (reuse, pre-scores)

    int b = blockIdx.x, tid = threadIdx.x;
    const float* uvb = g_uv + (size_t)b * (TT * NUV);

    // phase 0: coalesced base load -> sBase
    for (int idx = tid; idx < TP * 32; idx += 288) {
        int i = idx >> 5, c4 = (idx & 31) << 2;
        float4 v = make_float4(0.f, 0.f, 0.f, 0.f);
        if (i < TT) v = *(const float4*)(uvb + (size_t)i * NUV + 2*EE + c4);
        *(float4*)(sBase + i*132 + c4) = v;
    }
    __syncthreads();
    // phase 1: build transposed q,k (zero pad rows >= T so Ker pads are 0)
    for (int idx = tid; idx < SS * TP; idx += 288) {
        int s = idx / TP, i = idx - s * TP;
        float qv = 0.f, kv = 0.f;
        if (i < TT) {
            float v = sBase[i*132 + s];
            qv = fmaf(v, __ldg(gamma + s),       __ldg(beta + s));
            kv = fmaf(v, __ldg(gamma + SS + s),  __ldg(beta + SS + s));
        }
        sQT[s*TP + i] = qv;
        sKT[s*TP + i] = kv;
    }
    __syncthreads();
    // phase 2: scores -> Ker = relu(q.k/sqrt(S))^2, stored transposed
    for (int tile = tid; tile < 289; tile += 288) {
        int ti = tile / 17, tj = tile - ti * 17;
        int ia = ti*4, ib = 68 + ti*4, ja = tj*4, jb = 68 + tj*4;
        ull acc[8][4];
#pragma unroll
        for (int r = 0; r < 8; r++)
#pragma unroll
            for (int c = 0; c < 4; c++) acc[r][c] = 0ull;
#pragma unroll 4
        for (int s = 0; s < SS; s++) {
            float4 a0 = *(const float4*)(sQT + s*TP + ia);
            float4 a1 = *(const float4*)(sQT + s*TP + ib);
            float4 b0 = *(const float4*)(sKT + s*TP + ja);
            float4 b1 = *(const float4*)(sKT + s*TP + jb);
            mstep(acc, a0, a1, b0, b1);
        }
#pragma unroll
        for (int r = 0; r < 8; r++) {
            int i = (r < 4) ? (ia + r) : (ib + r - 4);
#pragma unroll
            for (int cp = 0; cp < 4; cp++) {
                float v0, v1; upk(acc[r][cp], v0, v1);
                int c0 = 2*cp, c1 = c0 + 1;
                int j0 = (c0 < 4) ? (ja + c0) : (jb + c0 - 4);
                int j1 = (c1 < 4) ? (ja + c1) : (jb + c1 - 4);
                float r0 = fmaxf(v0 * INV_SQRT_S, 0.f);
                float r1 = fmaxf(v1 * INV_SQRT_S, 0.f);
                sKerT[j0*140 + i] = r0 * r0;
                sKerT[j1*140 + i] = r1 * r1;
            }
        }
    }
    __syncthreads();
    // phase 3: attn = Ker @ v, h = u*attn, streamed in 4 E-chunks of 128
    int tr = tid >> 4, tc = tid & 15;
    for (int ch = 0; ch < 4; ch++) {
        int e0 = ch << 7;
        for (int idx = tid; idx < TP * 32; idx += 288) {
            int i = idx >> 5, c4 = (idx & 31) << 2;
            float4 v = make_float4(0.f, 0.f, 0.f, 0.f);
            if (i < TT) v = *(const float4*)(uvb + (size_t)i * NUV + EE + e0 + c4);
            *(float4*)(sV + i*132 + c4) = v;
        }
        __syncthreads();
        if (tr < 17) {
            int ia = tr*4, ib = 68 + tr*4, ea = tc*4, eb = 64 + tc*4;
            ull acc[8][4];
#pragma unroll
            for (int r = 0; r < 8; r++)
#pragma unroll
                for (int c = 0; c < 4; c++) acc[r][c] = 0ull;
#pragma unroll 2
            for (int j = 0; j < TP; j++) {
                float4 a0 = *(const float4*)(sKerT + j*140 + ia);
                float4 a1 = *(const float4*)(sKerT + j*140 + ib);
                float4 b0 = *(const float4*)(sV + j*132 + ea);
                float4 b1 = *(const float4*)(sV + j*132 + eb);
                mstep(acc, a0, a1, b0, b1);
            }
#pragma unroll
            for (int r = 0; r < 8; r++) {
                int i = (r < 4) ? (ia + r) : (ib + r - 4);
                if (i < TT) {
                    float v0, v1, v2, v3;
                    upk(acc[r][0], v0, v1); upk(acc[r][1], v2, v3);
                    float4 u4 = *(const float4*)(uvb + (size_t)i * NUV + e0 + ea);
                    float4 h4 = make_float4(v0*u4.x, v1*u4.y, v2*u4.z, v3*u4.w);
                    *(float4*)(g_h + (size_t)(b*TT + i) * EE + e0 + ea) = h4;
                    upk(acc[r][2], v0, v1); upk(acc[r][3], v2, v3);
                    u4 = *(const float4*)(uvb + (size_t)i * NUV + e0 + eb);
                    h4 = make_float4(v0*u4.x, v1*u4.y, v2*u4.z, v3*u4.w);
                    *(float4*)(g_h + (size_t)(b*TT + i) * EE + e0 + eb) = h4;
                }
            }
        }
        __syncthreads();
    }
}

// ---------------- kernel 3: out = h @ W_o^T + x*res_scale ------------------
// M=136192, N=256 (2 tiles), K=512. BK=16.
__global__ __launch_bounds__(256, 2)
void k_gemm_out(const float* __restrict__ Wo, const float* __restrict__ x,
                const float* __restrict__ res, float* __restrict__ out) {
    __shared__ float As[16][128];
    __shared__ float Bs[16][128];
    int tid = threadIdx.x;
    int m0 = blockIdx.x * 128, n0 = blockIdx.y * 128;
    int lr = tid >> 2;
    int lc = (tid & 3) * 4;
    const float* gA0 = g_h + (size_t)(m0 + lr)      * EE + lc;
    const float* gA1 = g_h + (size_t)(m0 + lr + 64) * EE + lc;
    const float* gB0 = Wo  + (size_t)(n0 + lr)      * EE + lc;
    const float* gB1 = Wo  + (size_t)(n0 + lr + 64) * EE + lc;
    int ty = tid >> 4, tx = tid & 15;

    ull acc[8][4];
#pragma unroll
    for (int r = 0; r < 8; r++)
#pragma unroll
        for (int c = 0; c < 4; c++) acc[r][c] = 0ull;

    for (int kt = 0; kt < EE; kt += 16) {
        float4 a0 = *(const float4*)(gA0 + kt);
        float4 a1 = *(const float4*)(gA1 + kt);
        float4 b0 = *(const float4*)(gB0 + kt);
        float4 b1 = *(const float4*)(gB1 + kt);
        __syncthreads();
        As[lc+0][lr] = a0.x; As[lc+1][lr] = a0.y;
        As[lc+2][lr] = a0.z; As[lc+3][lr] = a0.w;
        As[lc+0][lr+64] = a1.x; As[lc+1][lr+64] = a1.y;
        As[lc+2][lr+64] = a1.z; As[lc+3][lr+64] = a1.w;
        Bs[lc+0][lr] = b0.x; Bs[lc+1][lr] = b0.y;
        Bs[lc+2][lr] = b0.z; Bs[lc+3][lr] = b0.w;
        Bs[lc+0][lr+64] = b1.x; Bs[lc+1][lr+64] = b1.y;
        Bs[lc+2][lr+64] = b1.z; Bs[lc+3][lr+64] = b1.w;
        __syncthreads();
#pragma unroll
        for (int k = 0; k < 16; k++) {
            float4 ra0 = *(const float4*)&As[k][ty*4];
            float4 ra1 = *(const float4*)&As[k][64 + ty*4];
            float4 rb0 = *(const float4*)&Bs[k][tx*4];
            float4 rb1 = *(const float4*)&Bs[k][64 + tx*4];
            mstep(acc, ra0, ra1, rb0, rb1);
        }
    }
#pragma unroll
    for (int r = 0; r < 8; r++) {
        int m = m0 + ((r < 4) ? (ty*4 + r) : (64 + ty*4 + r - 4));
        float v0, v1, v2, v3;
        {
            upk(acc[r][0], v0, v1); upk(acc[r][1], v2, v3);
            float4 xa = *(const float4*)(x + (size_t)m * DD + n0 + tx*4);
            float4 ra = *(const float4*)(res + n0 + tx*4);
            float4 o = make_float4(v0 + xa.x*ra.x, v1 + xa.y*ra.y,
                                   v2 + xa.z*ra.z, v3 + xa.w*ra.w);
            *(float4*)(out + (size_t)m * DD + n0 + tx*4) = o;
        }
        {
            upk(acc[r][2], v0, v1); upk(acc[r][3], v2, v3);
            float4 xa = *(const float4*)(x + (size_t)m * DD + n0 + 64 + tx*4);
            float4 ra = *(const float4*)(res + n0 + 64 + tx*4);
            float4 o = make_float4(v0 + xa.x*ra.x, v1 + xa.y*ra.y,
                                   v2 + xa.z*ra.z, v3 + xa.w*ra.w);
            *(float4*)(out + (size_t)m * DD + n0 + 64 + tx*4) = o;
        }
    }
}

// ---------------- launch ----------------------------------------------------
extern "C" void kernel_launch(void* const* d_in, const int* in_sizes, int n_in,
                              void* d_out, int out_size) {
    (void)in_sizes; (void)n_in; (void)out_size;
    const float* x     = (const float*)d_in[0];
    const float* W_uv  = (const float*)d_in[1];
    const float* W_o   = (const float*)d_in[2];
    const float* gamma = (const float*)d_in[3];
    const float* beta  = (const float*)d_in[4];
    const float* g     = (const float*)d_in[5];
    const float* res   = (const float*)d_in[6];
    float* out = (float*)d_out;

    cudaFuncSetAttribute(k_attn, cudaFuncAttributeMaxDynamicSharedMemorySize,
                         SM_FLOATS * (int)sizeof(float));

    k_rnorm<<<MTOT / 8, dim3(32, 8)>>>(x, g);
    k_gemm_uv<<<dim3(MTOT / 128, NUV / 128), 256>>>(x, W_uv);
    k_attn<<<BATCH, 288, SM_FLOATS * (int)sizeof(float)>>>(gamma, beta);
    k_gemm_out<<<dim3(MTOT / 128, DD / 128), 256>>>(W_o, x, res, out);
}

// round 5
// speedup vs baseline: 1.1063x; 1.1063x over previous
#include <cuda_runtime.h>
#include <cuda_bf16.h>
#include <cstdint>

#define BATCH 1024
#define TT    133
#define TP    136
#define DD    256
#define EE    512
#define SS    128
#define NUV   1152
#define MTOT  (BATCH*TT)     // 136192
#define INV_SQRT_S 0.08838834764831845f
#define EPSV  1e-5f

typedef unsigned long long ull;

// ---------------- scratch ----------------------------------------------------
__device__ float g_rn[MTOT];
__device__ float g_uv[(size_t)MTOT * NUV];
__device__ __align__(16) __nv_bfloat16 g_xh[(size_t)MTOT * DD];
__device__ __align__(16) __nv_bfloat16 g_xl[(size_t)MTOT * DD];
__device__ __align__(16) __nv_bfloat16 g_wh[(size_t)NUV * DD];
__device__ __align__(16) __nv_bfloat16 g_wl[(size_t)NUV * DD];
__device__ __align__(16) __nv_bfloat16 g_woh[(size_t)DD * EE];
__device__ __align__(16) __nv_bfloat16 g_wol[(size_t)DD * EE];
__device__ __align__(16) __nv_bfloat16 g_hh[(size_t)MTOT * EE];
__device__ __align__(16) __nv_bfloat16 g_hl[(size_t)MTOT * EE];

// ---------------- helpers ----------------------------------------------------
__device__ __forceinline__ float silu_f(float v) { return v / (1.0f + __expf(-v)); }
__device__ __forceinline__ void split1(float v, __nv_bfloat16 &h, __nv_bfloat16 &l) {
    h = __float2bfloat16(v);
    l = __float2bfloat16(v - __bfloat162float(h));
}
__device__ __forceinline__ void mma16816(float (&d)[4], const uint32_t (&a)[4],
                                         uint32_t b0, uint32_t b1) {
    asm volatile("mma.sync.aligned.m16n8k16.row.col.f32.bf16.bf16.f32 "
                 "{%0,%1,%2,%3}, {%4,%5,%6,%7}, {%8,%9}, {%0,%1,%2,%3};"
                 : "+f"(d[0]), "+f"(d[1]), "+f"(d[2]), "+f"(d[3])
                 : "r"(a[0]), "r"(a[1]), "r"(a[2]), "r"(a[3]), "r"(b0), "r"(b1));
}

// ---------------- packed fp32x2 (attention) ---------------------------------
__device__ __forceinline__ ull pk2(float x, float y) {
    ull r; asm("mov.b64 %0, {%1, %2};" : "=l"(r) : "f"(x), "f"(y)); return r;
}
__device__ __forceinline__ void upk(ull v, float &x, float &y) {
    asm("mov.b64 {%0, %1}, %2;" : "=f"(x), "=f"(y) : "l"(v));
}
__device__ __forceinline__ void fma2(ull &d, ull a, ull b) {
    asm("fma.rn.f32x2 %0, %1, %2, %0;" : "+l"(d) : "l"(a), "l"(b));
}
__device__ __forceinline__ void mstep(ull (&acc)[8][4], float4 a0, float4 a1,
                                      float4 b0, float4 b1) {
    ull bp[4];
    bp[0] = pk2(b0.x, b0.y); bp[1] = pk2(b0.z, b0.w);
    bp[2] = pk2(b1.x, b1.y); bp[3] = pk2(b1.z, b1.w);
    float av[8] = {a0.x, a0.y, a0.z, a0.w, a1.x, a1.y, a1.z, a1.w};
#pragma unroll
    for (int r = 0; r < 8; r++) {
        ull ad = pk2(av[r], av[r]);
#pragma unroll
        for (int c = 0; c < 4; c++) fma2(acc[r][c], ad, bp[c]);
    }
}

// ---------------- kernel: row norm scale ------------------------------------
__global__ void k_rnorm(const float* __restrict__ x, const float* __restrict__ g) {
    int row = blockIdx.x * 8 + threadIdx.y;
    if (row >= MTOT) return;
    const float4* xr = (const float4*)(x + (size_t)row * DD);
    float s = 0.f;
#pragma unroll
    for (int i = threadIdx.x; i < 64; i += 32) {
        float4 v = xr[i];
        s += v.x*v.x + v.y*v.y + v.z*v.z + v.w*v.w;
    }
#pragma unroll
    for (int o = 16; o; o >>= 1) s += __shfl_xor_sync(0xffffffffu, s, o);
    if (threadIdx.x == 0) {
        float norm = sqrtf(s) * 0.0625f;
        g_rn[row] = g[0] / fmaxf(norm, EPSV);
    }
}

// ---------------- split kernels ---------------------------------------------
__global__ void k_split_x(const float* __restrict__ x) {
    size_t idx = (size_t)blockIdx.x * 256 + threadIdx.x;   // MTOT*64 float4s
    int row = (int)(idx >> 6);
    float s = g_rn[row];
    float4 v = ((const float4*)x)[idx];
    __nv_bfloat16 h0,h1,h2,h3,l0,l1,l2,l3;
    split1(v.x*s,h0,l0); split1(v.y*s,h1,l1); split1(v.z*s,h2,l2); split1(v.w*s,h3,l3);
    __nv_bfloat162* dh = (__nv_bfloat162*)(g_xh + idx*4);
    __nv_bfloat162* dl = (__nv_bfloat162*)(g_xl + idx*4);
    dh[0] = __nv_bfloat162(h0,h1); dh[1] = __nv_bfloat162(h2,h3);
    dl[0] = __nv_bfloat162(l0,l1); dl[1] = __nv_bfloat162(l2,l3);
}

__global__ void k_split_w(const float* __restrict__ Wuv, const float* __restrict__ Wo) {
    int idx = blockIdx.x * 256 + threadIdx.x;
    const int N1 = NUV * DD / 4;
    const int N2 = DD * EE / 4;
    if (idx < N1) {
        float4 v = ((const float4*)Wuv)[idx];
        __nv_bfloat16 h0,h1,h2,h3,l0,l1,l2,l3;
        split1(v.x,h0,l0); split1(v.y,h1,l1); split1(v.z,h2,l2); split1(v.w,h3,l3);
        __nv_bfloat162* ph = (__nv_bfloat162*)(g_wh + (size_t)idx*4);
        __nv_bfloat162* pl = (__nv_bfloat162*)(g_wl + (size_t)idx*4);
        ph[0] = __nv_bfloat162(h0,h1); ph[1] = __nv_bfloat162(h2,h3);
        pl[0] = __nv_bfloat162(l0,l1); pl[1] = __nv_bfloat162(l2,l3);
    } else if (idx < N1 + N2) {
        int j = idx - N1;
        float4 v = ((const float4*)Wo)[j];
        __nv_bfloat16 h0,h1,h2,h3,l0,l1,l2,l3;
        split1(v.x,h0,l0); split1(v.y,h1,l1); split1(v.z,h2,l2); split1(v.w,h3,l3);
        __nv_bfloat162* ph = (__nv_bfloat162*)(g_woh + (size_t)j*4);
        __nv_bfloat162* pl = (__nv_bfloat162*)(g_wol + (size_t)j*4);
        ph[0] = __nv_bfloat162(h0,h1); ph[1] = __nv_bfloat162(h2,h3);
        pl[0] = __nv_bfloat162(l0,l1); pl[1] = __nv_bfloat162(l2,l3);
    }
}

// ---------------- mma.sync bf16-split GEMM (explicit-LDS, double-buffered) --
// GEMM==0: g_uv = silu([xh|xl] @ [wh|wl]^T), K=256, N=1152  (out ptr taken
//          from the device global INSIDE the kernel — never from host!)
// GEMM==1: out  = [hh|hl] @ [woh|wol]^T + x*res, K=512, N=256
#define STRIDE 40   // padded smem row stride in bf16 elements (32 data + 8 pad)

template<int GEMM>
__global__ __launch_bounds__(256)
void k_gemm_mma(const float* __restrict__ x, const float* __restrict__ res,
                float* __restrict__ outp_param) {
    constexpr int KREAL = (GEMM == 0) ? 256 : 512;
    constexpr int LDC   = (GEMM == 0) ? NUV : DD;
    constexpr int KC    = KREAL / 32;
    constexpr int NC    = 3 * KC;
    const __nv_bfloat16* Ah = (GEMM == 0) ? g_xh : g_hh;
    const __nv_bfloat16* Al = (GEMM == 0) ? g_xl : g_hl;
    const __nv_bfloat16* Bh = (GEMM == 0) ? g_wh : g_woh;
    const __nv_bfloat16* Bl = (GEMM == 0) ? g_wl : g_wol;
    float* outp = (GEMM == 0) ? g_uv : outp_param;   // device-side symbol ref

    __shared__ __align__(16) __nv_bfloat16 sA[2][128 * STRIDE];
    __shared__ __align__(16) __nv_bfloat16 sB[2][128 * STRIDE];

    int tid = threadIdx.x, lane = tid & 31, wid = tid >> 5;
    int m0 = blockIdx.y * 128, n0 = blockIdx.x * 128;
    int wm = (wid & 1) * 64, wn = (wid >> 1) * 32;
    int qr = lane >> 2;            // lane/4
    int qc = (lane & 3) * 2;       // 2*(lane%4)

    float acc[4][4][4];
#pragma unroll
    for (int i = 0; i < 4; i++)
#pragma unroll
        for (int j = 0; j < 4; j++)
#pragma unroll
            for (int k = 0; k < 4; k++) acc[i][j][k] = 0.f;

    uint4 pA[2], pB[2];

#define LOADR(c) do { \
    int term = (c) / KC; \
    int kk = ((c) % KC) * 32; \
    const __nv_bfloat16* a_ = (term == 1) ? Al : Ah; \
    const __nv_bfloat16* b_ = (term == 2) ? Bl : Bh; \
    _Pragma("unroll") \
    for (int i = 0; i < 2; i++) { \
        int idx = tid * 2 + i; \
        int row = idx >> 2, u = idx & 3; \
        pA[i] = *(const uint4*)(a_ + (size_t)(m0 + row) * KREAL + kk + u * 8); \
        pB[i] = *(const uint4*)(b_ + (size_t)(n0 + row) * KREAL + kk + u * 8); \
    } \
} while (0)

#define STOREB(s) do { \
    _Pragma("unroll") \
    for (int i = 0; i < 2; i++) { \
        int idx = tid * 2 + i; \
        int row = idx >> 2, u = idx & 3; \
        *(uint4*)(&sA[s][row * STRIDE + u * 8]) = pA[i]; \
        *(uint4*)(&sB[s][row * STRIDE + u * 8]) = pB[i]; \
    } \
} while (0)

    LOADR(0); STOREB(0);
    __syncthreads();

    for (int c = 0; c < NC; c++) {
        int s = c & 1;
        if (c + 1 < NC) LOADR(c + 1);
#pragma unroll
        for (int ks = 0; ks < 2; ks++) {
            int kel = ks * 16 + qc;
            uint32_t bf[4][2];
#pragma unroll
            for (int nt = 0; nt < 4; nt++) {
                int nr = wn + nt * 8 + qr;
                bf[nt][0] = *(const uint32_t*)(&sB[s][nr * STRIDE + kel]);
                bf[nt][1] = *(const uint32_t*)(&sB[s][nr * STRIDE + kel + 8]);
            }
#pragma unroll
            for (int mt = 0; mt < 4; mt++) {
                int mr = wm + mt * 16 + qr;
                uint32_t af[4];
                af[0] = *(const uint32_t*)(&sA[s][mr * STRIDE + kel]);
                af[1] = *(const uint32_t*)(&sA[s][(mr + 8) * STRIDE + kel]);
                af[2] = *(const uint32_t*)(&sA[s][mr * STRIDE + kel + 8]);
                af[3] = *(const uint32_t*)(&sA[s][(mr + 8) * STRIDE + kel + 8]);
#pragma unroll
                for (int nt = 0; nt < 4; nt++)
                    mma16816(acc[mt][nt], af, bf[nt][0], bf[nt][1]);
            }
        }
        if (c + 1 < NC) {
            __syncthreads();          // readers of next buffer done
            STOREB((c + 1) & 1);
            __syncthreads();          // new data visible
        }
    }
#undef LOADR
#undef STOREB

#pragma unroll
    for (int mt = 0; mt < 4; mt++) {
#pragma unroll
        for (int nt = 0; nt < 4; nt++) {
            int gm = m0 + wm + mt * 16 + qr;
            int gn = n0 + wn + nt * 8 + qc;
            float* d = acc[mt][nt];
            if (GEMM == 0) {
                float2 o0 = make_float2(silu_f(d[0]), silu_f(d[1]));
                float2 o1 = make_float2(silu_f(d[2]), silu_f(d[3]));
                *(float2*)(outp + (size_t)gm * LDC + gn) = o0;
                *(float2*)(outp + (size_t)(gm + 8) * LDC + gn) = o1;
            } else {
                float2 xa0 = *(const float2*)(x + (size_t)gm * DD + gn);
                float2 xa1 = *(const float2*)(x + (size_t)(gm + 8) * DD + gn);
                float2 rr  = *(const float2*)(res + gn);
                float2 o0 = make_float2(d[0] + xa0.x * rr.x, d[1] + xa0.y * rr.y);
                float2 o1 = make_float2(d[2] + xa1.x * rr.x, d[3] + xa1.y * rr.y);
                *(float2*)(outp + (size_t)gm * LDC + gn) = o0;
                *(float2*)(outp + (size_t)(gm + 8) * LDC + gn) = o1;
            }
        }
    }
}

// ---------------- attention (FFMA2; writes bf16-split h) --------------------
#define SM_KERT 0
#define SM_QT   (136*140)
#define SM_KT   (SM_QT + 128*136)
#define SM_FLOATS (SM_KT + 128*136)

__global__ __launch_bounds__(288, 1)
void k_attn(const float* __restrict__ gamma, const float* __restrict__ beta) {
    extern __shared__ float sm[];
    float* sKerT = sm + SM_KERT;
    float* sQT   = sm + SM_QT;
    float* sKT   = sm + SM_KT;
    float* sV    = sQT;
    float* sBase = sKerT;

    int b = blockIdx.x, tid = threadIdx.x;
    const float* uvb = g_uv + (size_t)b * (TT * NUV);

    for (int idx = tid; idx < TP * 32; idx += 288) {
        int i = idx >> 5, c4 = (idx & 31) << 2;
        float4 v = make_float4(0.f, 0.f, 0.f, 0.f);
        if (i < TT) v = *(const float4*)(uvb + (size_t)i * NUV + 2*EE + c4);
        *(float4*)(sBase + i*132 + c4) = v;
    }
    __syncthreads();
    for (int idx = tid; idx < SS * TP; idx += 288) {
        int s = idx / TP, i = idx - s * TP;
        float qv = 0.f, kv = 0.f;
        if (i < TT) {
            float v = sBase[i*132 + s];
            qv = fmaf(v, __ldg(gamma + s),      __ldg(beta + s));
            kv = fmaf(v, __ldg(gamma + SS + s), __ldg(beta + SS + s));
        }
        sQT[s*TP + i] = qv;
        sKT[s*TP + i] = kv;
    }
    __syncthreads();
    for (int tile = tid; tile < 289; tile += 288) {
        int ti = tile / 17, tj = tile - ti * 17;
        int ia = ti*4, ib = 68 + ti*4, ja = tj*4, jb = 68 + tj*4;
        ull acc[8][4];
#pragma unroll
        for (int r = 0; r < 8; r++)
#pragma unroll
            for (int c = 0; c < 4; c++) acc[r][c] = 0ull;
#pragma unroll 4
        for (int s = 0; s < SS; s++) {
            float4 a0 = *(const float4*)(sQT + s*TP + ia);
            float4 a1 = *(const float4*)(sQT + s*TP + ib);
            float4 b0 = *(const float4*)(sKT + s*TP + ja);
            float4 b1 = *(const float4*)(sKT + s*TP + jb);
            mstep(acc, a0, a1, b0, b1);
        }
#pragma unroll
        for (int r = 0; r < 8; r++) {
            int i = (r < 4) ? (ia + r) : (ib + r - 4);
#pragma unroll
            for (int cp = 0; cp < 4; cp++) {
                float v0, v1; upk(acc[r][cp], v0, v1);
                int cc0 = 2*cp, cc1 = cc0 + 1;
                int j0 = (cc0 < 4) ? (ja + cc0) : (jb + cc0 - 4);
                int j1 = (cc1 < 4) ? (ja + cc1) : (jb + cc1 - 4);
                float r0 = fmaxf(v0 * INV_SQRT_S, 0.f);
                float r1 = fmaxf(v1 * INV_SQRT_S, 0.f);
                sKerT[j0*140 + i] = r0 * r0;
                sKerT[j1*140 + i] = r1 * r1;
            }
        }
    }
    __syncthreads();
    int tr = tid >> 4, tc = tid & 15;
    for (int ch = 0; ch < 4; ch++) {
        int e0 = ch << 7;
        for (int idx = tid; idx < TP * 32; idx += 288) {
            int i = idx >> 5, c4 = (idx & 31) << 2;
            float4 v = make_float4(0.f, 0.f, 0.f, 0.f);
            if (i < TT) v = *(const float4*)(uvb + (size_t)i * NUV + EE + e0 + c4);
            *(float4*)(sV + i*132 + c4) = v;
        }
        __syncthreads();
        if (tr < 17) {
            int ia = tr*4, ib = 68 + tr*4, ea = tc*4, eb = 64 + tc*4;
            ull acc[8][4];
#pragma unroll
            for (int r = 0; r < 8; r++)
#pragma unroll
                for (int c = 0; c < 4; c++) acc[r][c] = 0ull;
#pragma unroll 2
            for (int j = 0; j < TP; j++) {
                float4 a0 = *(const float4*)(sKerT + j*140 + ia);
                float4 a1 = *(const float4*)(sKerT + j*140 + ib);
                float4 b0 = *(const float4*)(sV + j*132 + ea);
                float4 b1 = *(const float4*)(sV + j*132 + eb);
                mstep(acc, a0, a1, b0, b1);
            }
#pragma unroll
            for (int r = 0; r < 8; r++) {
                int i = (r < 4) ? (ia + r) : (ib + r - 4);
                if (i < TT) {
                    size_t ro = (size_t)(b*TT + i) * EE;
#pragma unroll
                    for (int half = 0; half < 2; half++) {
                        float v0, v1, v2, v3;
                        upk(acc[r][half*2+0], v0, v1); upk(acc[r][half*2+1], v2, v3);
                        int ec = (half == 0) ? ea : eb;
                        float4 u4 = *(const float4*)(uvb + (size_t)i * NUV + e0 + ec);
                        float h0 = v0*u4.x, h1 = v1*u4.y, h2 = v2*u4.z, h3 = v3*u4.w;
                        __nv_bfloat16 a0b,a1b,a2b,a3b,l0,l1,l2,l3;
                        split1(h0,a0b,l0); split1(h1,a1b,l1);
                        split1(h2,a2b,l2); split1(h3,a3b,l3);
                        __nv_bfloat162* dh = (__nv_bfloat162*)(g_hh + ro + e0 + ec);
                        __nv_bfloat162* dl = (__nv_bfloat162*)(g_hl + ro + e0 + ec);
                        dh[0] = __nv_bfloat162(a0b,a1b); dh[1] = __nv_bfloat162(a2b,a3b);
                        dl[0] = __nv_bfloat162(l0,l1);   dl[1] = __nv_bfloat162(l2,l3);
                    }
                }
            }
        }
        __syncthreads();
    }
}

// ---------------- launch ----------------------------------------------------
extern "C" void kernel_launch(void* const* d_in, const int* in_sizes, int n_in,
                              void* d_out, int out_size) {
    (void)in_sizes; (void)n_in; (void)out_size;
    const float* x     = (const float*)d_in[0];
    const float* W_uv  = (const float*)d_in[1];
    const float* W_o   = (const float*)d_in[2];
    const float* gamma = (const float*)d_in[3];
    const float* beta  = (const float*)d_in[4];
    const float* g     = (const float*)d_in[5];
    const float* res   = (const float*)d_in[6];
    float* out = (float*)d_out;

    cudaFuncSetAttribute(k_attn, cudaFuncAttributeMaxDynamicSharedMemorySize,
                         SM_FLOATS * (int)sizeof(float));

    k_rnorm<<<MTOT / 8, dim3(32, 8)>>>(x, g);
    k_split_x<<<MTOT * 64 / 256, 256>>>(x);
    k_split_w<<<(NUV * 64 + DD * 128 + 255) / 256, 256>>>(W_uv, W_o);
    k_gemm_mma<0><<<dim3(NUV / 128, MTOT / 128), 256>>>(nullptr, nullptr, nullptr);
    k_attn<<<BATCH, 288, SM_FLOATS * (int)sizeof(float)>>>(gamma, beta);
    k_gemm_mma<1><<<dim3(DD / 128, MTOT / 128), 256>>>(x, res, out);
}

// round 6
// speedup vs baseline: 1.1336x; 1.0247x over previous
#include <cuda_runtime.h>
#include <cuda_bf16.h>
#include <cstdint>

#define BATCH 1024
#define TT    133
#define DD    256
#define EE    512
#define SS    128
#define NUV   1152
#define MTOT  (BATCH*TT)     // 136192
#define INV_SQRT_S 0.08838834764831845f
#define EPSV  1e-5f

typedef unsigned long long ull;

// ---------------- scratch ----------------------------------------------------
__device__ float g_rn[MTOT];
__device__ float g_uv[(size_t)MTOT * NUV];
__device__ __align__(16) __nv_bfloat16 g_xh[(size_t)MTOT * DD];
__device__ __align__(16) __nv_bfloat16 g_xl[(size_t)MTOT * DD];
__device__ __align__(16) __nv_bfloat16 g_wh[(size_t)NUV * DD];
__device__ __align__(16) __nv_bfloat16 g_wl[(size_t)NUV * DD];
__device__ __align__(16) __nv_bfloat16 g_woh[(size_t)DD * EE];
__device__ __align__(16) __nv_bfloat16 g_wol[(size_t)DD * EE];
__device__ __align__(16) __nv_bfloat16 g_hh[(size_t)MTOT * EE];
__device__ __align__(16) __nv_bfloat16 g_hl[(size_t)MTOT * EE];

// ---------------- helpers ----------------------------------------------------
__device__ __forceinline__ float silu_f(float v) { return v / (1.0f + __expf(-v)); }
__device__ __forceinline__ void split1(float v, __nv_bfloat16 &h, __nv_bfloat16 &l) {
    h = __float2bfloat16(v);
    l = __float2bfloat16(v - __bfloat162float(h));
}
__device__ __forceinline__ void mma16816(float (&d)[4], const uint32_t (&a)[4],
                                         uint32_t b0, uint32_t b1) {
    asm volatile("mma.sync.aligned.m16n8k16.row.col.f32.bf16.bf16.f32 "
                 "{%0,%1,%2,%3}, {%4,%5,%6,%7}, {%8,%9}, {%0,%1,%2,%3};"
                 : "+f"(d[0]), "+f"(d[1]), "+f"(d[2]), "+f"(d[3])
                 : "r"(a[0]), "r"(a[1]), "r"(a[2]), "r"(a[3]), "r"(b0), "r"(b1));
}
__device__ __forceinline__ uint32_t lds32(const __nv_bfloat16* p) {
    return *(const uint32_t*)p;
}

// ---------------- kernel: row norm scale ------------------------------------
__global__ void k_rnorm(const float* __restrict__ x, const float* __restrict__ g) {
    int row = blockIdx.x * 8 + threadIdx.y;
    if (row >= MTOT) return;
    const float4* xr = (const float4*)(x + (size_t)row * DD);
    float s = 0.f;
#pragma unroll
    for (int i = threadIdx.x; i < 64; i += 32) {
        float4 v = xr[i];
        s += v.x*v.x + v.y*v.y + v.z*v.z + v.w*v.w;
    }
#pragma unroll
    for (int o = 16; o; o >>= 1) s += __shfl_xor_sync(0xffffffffu, s, o);
    if (threadIdx.x == 0) {
        float norm = sqrtf(s) * 0.0625f;
        g_rn[row] = g[0] / fmaxf(norm, EPSV);
    }
}

// ---------------- split kernels ---------------------------------------------
__global__ void k_split_x(const float* __restrict__ x) {
    size_t idx = (size_t)blockIdx.x * 256 + threadIdx.x;
    int row = (int)(idx >> 6);
    float s = g_rn[row];
    float4 v = ((const float4*)x)[idx];
    __nv_bfloat16 h0,h1,h2,h3,l0,l1,l2,l3;
    split1(v.x*s,h0,l0); split1(v.y*s,h1,l1); split1(v.z*s,h2,l2); split1(v.w*s,h3,l3);
    __nv_bfloat162* dh = (__nv_bfloat162*)(g_xh + idx*4);
    __nv_bfloat162* dl = (__nv_bfloat162*)(g_xl + idx*4);
    dh[0] = __nv_bfloat162(h0,h1); dh[1] = __nv_bfloat162(h2,h3);
    dl[0] = __nv_bfloat162(l0,l1); dl[1] = __nv_bfloat162(l2,l3);
}

__global__ void k_split_w(const float* __restrict__ Wuv, const float* __restrict__ Wo) {
    int idx = blockIdx.x * 256 + threadIdx.x;
    const int N1 = NUV * DD / 4;
    const int N2 = DD * EE / 4;
    if (idx < N1) {
        float4 v = ((const float4*)Wuv)[idx];
        __nv_bfloat16 h0,h1,h2,h3,l0,l1,l2,l3;
        split1(v.x,h0,l0); split1(v.y,h1,l1); split1(v.z,h2,l2); split1(v.w,h3,l3);
        __nv_bfloat162* ph = (__nv_bfloat162*)(g_wh + (size_t)idx*4);
        __nv_bfloat162* pl = (__nv_bfloat162*)(g_wl + (size_t)idx*4);
        ph[0] = __nv_bfloat162(h0,h1); ph[1] = __nv_bfloat162(h2,h3);
        pl[0] = __nv_bfloat162(l0,l1); pl[1] = __nv_bfloat162(l2,l3);
    } else if (idx < N1 + N2) {
        int j = idx - N1;
        float4 v = ((const float4*)Wo)[j];
        __nv_bfloat16 h0,h1,h2,h3,l0,l1,l2,l3;
        split1(v.x,h0,l0); split1(v.y,h1,l1); split1(v.z,h2,l2); split1(v.w,h3,l3);
        __nv_bfloat162* ph = (__nv_bfloat162*)(g_woh + (size_t)j*4);
        __nv_bfloat162* pl = (__nv_bfloat162*)(g_wol + (size_t)j*4);
        ph[0] = __nv_bfloat162(h0,h1); ph[1] = __nv_bfloat162(h2,h3);
        pl[0] = __nv_bfloat162(l0,l1); pl[1] = __nv_bfloat162(l2,l3);
    }
}

// ---------------- mma.sync bf16-split GEMM (unchanged from round 5) ---------
#define STRIDE 40

template<int GEMM>
__global__ __launch_bounds__(256)
void k_gemm_mma(const float* __restrict__ x, const float* __restrict__ res,
                float* __restrict__ outp_param) {
    constexpr int KREAL = (GEMM == 0) ? 256 : 512;
    constexpr int LDC   = (GEMM == 0) ? NUV : DD;
    constexpr int KC    = KREAL / 32;
    constexpr int NC    = 3 * KC;
    const __nv_bfloat16* Ah = (GEMM == 0) ? g_xh : g_hh;
    const __nv_bfloat16* Al = (GEMM == 0) ? g_xl : g_hl;
    const __nv_bfloat16* Bh = (GEMM == 0) ? g_wh : g_woh;
    const __nv_bfloat16* Bl = (GEMM == 0) ? g_wl : g_wol;
    float* outp = (GEMM == 0) ? g_uv : outp_param;

    __shared__ __align__(16) __nv_bfloat16 sA[2][128 * STRIDE];
    __shared__ __align__(16) __nv_bfloat16 sB[2][128 * STRIDE];

    int tid = threadIdx.x, lane = tid & 31, wid = tid >> 5;
    int m0 = blockIdx.y * 128, n0 = blockIdx.x * 128;
    int wm = (wid & 1) * 64, wn = (wid >> 1) * 32;
    int qr = lane >> 2;
    int qc = (lane & 3) * 2;

    float acc[4][4][4];
#pragma unroll
    for (int i = 0; i < 4; i++)
#pragma unroll
        for (int j = 0; j < 4; j++)
#pragma unroll
            for (int k = 0; k < 4; k++) acc[i][j][k] = 0.f;

    uint4 pA[2], pB[2];

#define LOADR(c) do { \
    int term = (c) / KC; \
    int kk = ((c) % KC) * 32; \
    const __nv_bfloat16* a_ = (term == 1) ? Al : Ah; \
    const __nv_bfloat16* b_ = (term == 2) ? Bl : Bh; \
    _Pragma("unroll") \
    for (int i = 0; i < 2; i++) { \
        int idx = tid * 2 + i; \
        int row = idx >> 2, u = idx & 3; \
        pA[i] = *(const uint4*)(a_ + (size_t)(m0 + row) * KREAL + kk + u * 8); \
        pB[i] = *(const uint4*)(b_ + (size_t)(n0 + row) * KREAL + kk + u * 8); \
    } \
} while (0)

#define STOREB(s) do { \
    _Pragma("unroll") \
    for (int i = 0; i < 2; i++) { \
        int idx = tid * 2 + i; \
        int row = idx >> 2, u = idx & 3; \
        *(uint4*)(&sA[s][row * STRIDE + u * 8]) = pA[i]; \
        *(uint4*)(&sB[s][row * STRIDE + u * 8]) = pB[i]; \
    } \
} while (0)

    LOADR(0); STOREB(0);
    __syncthreads();

    for (int c = 0; c < NC; c++) {
        int s = c & 1;
        if (c + 1 < NC) LOADR(c + 1);
#pragma unroll
        for (int ks = 0; ks < 2; ks++) {
            int kel = ks * 16 + qc;
            uint32_t bf[4][2];
#pragma unroll
            for (int nt = 0; nt < 4; nt++) {
                int nr = wn + nt * 8 + qr;
                bf[nt][0] = lds32(&sB[s][nr * STRIDE + kel]);
                bf[nt][1] = lds32(&sB[s][nr * STRIDE + kel + 8]);
            }
#pragma unroll
            for (int mt = 0; mt < 4; mt++) {
                int mr = wm + mt * 16 + qr;
                uint32_t af[4];
                af[0] = lds32(&sA[s][mr * STRIDE + kel]);
                af[1] = lds32(&sA[s][(mr + 8) * STRIDE + kel]);
                af[2] = lds32(&sA[s][mr * STRIDE + kel + 8]);
                af[3] = lds32(&sA[s][(mr + 8) * STRIDE + kel + 8]);
#pragma unroll
                for (int nt = 0; nt < 4; nt++)
                    mma16816(acc[mt][nt], af, bf[nt][0], bf[nt][1]);
            }
        }
        if (c + 1 < NC) {
            __syncthreads();
            STOREB((c + 1) & 1);
            __syncthreads();
        }
    }
#undef LOADR
#undef STOREB

#pragma unroll
    for (int mt = 0; mt < 4; mt++) {
#pragma unroll
        for (int nt = 0; nt < 4; nt++) {
            int gm = m0 + wm + mt * 16 + qr;
            int gn = n0 + wn + nt * 8 + qc;
            float* d = acc[mt][nt];
            if (GEMM == 0) {
                float2 o0 = make_float2(silu_f(d[0]), silu_f(d[1]));
                float2 o1 = make_float2(silu_f(d[2]), silu_f(d[3]));
                *(float2*)(outp + (size_t)gm * LDC + gn) = o0;
                *(float2*)(outp + (size_t)(gm + 8) * LDC + gn) = o1;
            } else {
                float2 xa0 = *(const float2*)(x + (size_t)gm * DD + gn);
                float2 xa1 = *(const float2*)(x + (size_t)(gm + 8) * DD + gn);
                float2 rr  = *(const float2*)(res + gn);
                float2 o0 = make_float2(d[0] + xa0.x * rr.x, d[1] + xa0.y * rr.y);
                float2 o1 = make_float2(d[2] + xa1.x * rr.x, d[3] + xa1.y * rr.y);
                *(float2*)(outp + (size_t)gm * LDC + gn) = o0;
                *(float2*)(outp + (size_t)(gm + 8) * LDC + gn) = o1;
            }
        }
    }
}

// ---------------- attention v2: mma.sync bf16-split --------------------------
// One CTA (288 thr, 9 warps) per batch. T padded to 144 rows.
// smem element offsets (bf16 units):
//   phase A: qh[144][136]@0, ql@19584, kh@39168, kl@58752  (end 78336)
//   phase B: kernh[144][152]@0, kernl@21888  (overwrites q/k after full sync)
//            vth[128][152]@43776, vtl@63232  (end 82688 -> 165376 bytes)
#define O_QH   0
#define O_QL   19584
#define O_KH   39168
#define O_KL   58752
#define O_KERH 0
#define O_KERL 21888
#define O_VTH  43776
#define O_VTL  63232
#define AT_SMEM_BYTES (82688 * 2)
#define SQK 136
#define SKR 152

__global__ __launch_bounds__(288, 1)
void k_attn2(const float* __restrict__ gamma, const float* __restrict__ beta) {
    extern __shared__ __align__(16) __nv_bfloat16 sb[];
    int b = blockIdx.x, tid = threadIdx.x;
    int w = tid >> 5, lane = tid & 31;
    int qr = lane >> 2, qc = (lane & 3) * 2;
    const float* uvb = g_uv + (size_t)b * TT * NUV;

    // ---- phase A: build q/k hi-lo, rows >= TT zeroed ----
    for (int idx = tid; idx < 144 * 32; idx += 288) {
        int i = idx >> 5, s4 = (idx & 31) * 4;
        bool valid = (i < TT);
        float4 base = valid ? *(const float4*)(uvb + (size_t)i * NUV + 2*EE + s4)
                            : make_float4(0.f, 0.f, 0.f, 0.f);
        float4 ga = *(const float4*)(gamma + s4);
        float4 gk = *(const float4*)(gamma + SS + s4);
        float4 ba = *(const float4*)(beta + s4);
        float4 bk = *(const float4*)(beta + SS + s4);
        float q[4], k[4];
        q[0] = valid ? fmaf(base.x, ga.x, ba.x) : 0.f;
        q[1] = valid ? fmaf(base.y, ga.y, ba.y) : 0.f;
        q[2] = valid ? fmaf(base.z, ga.z, ba.z) : 0.f;
        q[3] = valid ? fmaf(base.w, ga.w, ba.w) : 0.f;
        k[0] = valid ? fmaf(base.x, gk.x, bk.x) : 0.f;
        k[1] = valid ? fmaf(base.y, gk.y, bk.y) : 0.f;
        k[2] = valid ? fmaf(base.z, gk.z, bk.z) : 0.f;
        k[3] = valid ? fmaf(base.w, gk.w, bk.w) : 0.f;
        __nv_bfloat16 qh[4], ql[4], kh[4], kl[4];
#pragma unroll
        for (int t = 0; t < 4; t++) { split1(q[t], qh[t], ql[t]); split1(k[t], kh[t], kl[t]); }
        int off = i * SQK + s4;
        *(__nv_bfloat162*)(sb + O_QH + off)     = __nv_bfloat162(qh[0], qh[1]);
        *(__nv_bfloat162*)(sb + O_QH + off + 2) = __nv_bfloat162(qh[2], qh[3]);
        *(__nv_bfloat162*)(sb + O_QL + off)     = __nv_bfloat162(ql[0], ql[1]);
        *(__nv_bfloat162*)(sb + O_QL + off + 2) = __nv_bfloat162(ql[2], ql[3]);
        *(__nv_bfloat162*)(sb + O_KH + off)     = __nv_bfloat162(kh[0], kh[1]);
        *(__nv_bfloat162*)(sb + O_KH + off + 2) = __nv_bfloat162(kh[2], kh[3]);
        *(__nv_bfloat162*)(sb + O_KL + off)     = __nv_bfloat162(kl[0], kl[1]);
        *(__nv_bfloat162*)(sb + O_KL + off + 2) = __nv_bfloat162(kl[2], kl[3]);
    }
    __syncthreads();

    // ---- scores: warp w owns rows [16w, 16w+16), 17 n-tiles ----
    float acc[17][4];
#pragma unroll
    for (int nt = 0; nt < 17; nt++)
#pragma unroll
        for (int t = 0; t < 4; t++) acc[nt][t] = 0.f;

    int m = w * 16 + qr;
#pragma unroll
    for (int t = 0; t < 3; t++) {
        const __nv_bfloat16* A = sb + ((t == 1) ? O_QL : O_QH);
        const __nv_bfloat16* B = sb + ((t == 2) ? O_KL : O_KH);
#pragma unroll
        for (int ks = 0; ks < 8; ks++) {
            int kel = ks * 16 + qc;
            uint32_t af[4];
            af[0] = lds32(A + m * SQK + kel);
            af[1] = lds32(A + (m + 8) * SQK + kel);
            af[2] = lds32(A + m * SQK + kel + 8);
            af[3] = lds32(A + (m + 8) * SQK + kel + 8);
#pragma unroll
            for (int nt = 0; nt < 17; nt++) {
                int n = nt * 8 + qr;
                uint32_t b0 = lds32(B + n * SQK + kel);
                uint32_t b1 = lds32(B + n * SQK + kel + 8);
                mma16816(acc[nt], af, b0, b1);
            }
        }
    }
    __syncthreads();   // everyone done reading q/k

    // ---- write kernel = relu(scores/sqrt(S))^2 as hi/lo; zero pad cols ----
#pragma unroll
    for (int nt = 0; nt < 17; nt++) {
        int col = nt * 8 + qc;
#pragma unroll
        for (int p = 0; p < 2; p++) {
            int row = m + p * 8;
            float v0 = fmaxf(acc[nt][2*p]     * INV_SQRT_S, 0.f);
            float v1 = fmaxf(acc[nt][2*p + 1] * INV_SQRT_S, 0.f);
            v0 *= v0; v1 *= v1;
            __nv_bfloat16 h0, l0, h1, l1;
            split1(v0, h0, l0); split1(v1, h1, l1);
            *(__nv_bfloat162*)(sb + O_KERH + row * SKR + col) = __nv_bfloat162(h0, h1);
            *(__nv_bfloat162*)(sb + O_KERL + row * SKR + col) = __nv_bfloat162(l0, l1);
        }
    }
    for (int idx = tid; idx < 144 * 4; idx += 288) {
        int row = idx >> 2, c = 136 + (idx & 3) * 2;
        *(__nv_bfloat162*)(sb + O_KERH + row * SKR + c) = __nv_bfloat162(__nv_bfloat16(0.f), __nv_bfloat16(0.f));
        *(__nv_bfloat162*)(sb + O_KERL + row * SKR + c) = __nv_bfloat162(__nv_bfloat16(0.f), __nv_bfloat16(0.f));
    }
    __syncthreads();

    // ---- attn = kernel @ v, fused h = u * attn, 4 E-chunks of 128 ----
    for (int ch = 0; ch < 4; ch++) {
        int e0 = ch * 128;
        // transposed split store of v chunk (cols j>=TT zeroed)
        for (int idx = tid; idx < 144 * 32; idx += 288) {
            int j = idx >> 5, e4 = (idx & 31) * 4;
            float4 v = (j < TT) ? *(const float4*)(uvb + (size_t)j * NUV + EE + e0 + e4)
                                : make_float4(0.f, 0.f, 0.f, 0.f);
            float vv[4] = {v.x, v.y, v.z, v.w};
#pragma unroll
            for (int t = 0; t < 4; t++) {
                __nv_bfloat16 h, l;
                split1(vv[t], h, l);
                sb[O_VTH + (e4 + t) * SKR + j] = h;
                sb[O_VTL + (e4 + t) * SKR + j] = l;
            }
        }
        __syncthreads();

        float acc2[16][4];
#pragma unroll
        for (int nt = 0; nt < 16; nt++)
#pragma unroll
            for (int t = 0; t < 4; t++) acc2[nt][t] = 0.f;

#pragma unroll
        for (int t = 0; t < 3; t++) {
            const __nv_bfloat16* A = sb + ((t == 1) ? O_KERL : O_KERH);
            const __nv_bfloat16* B = sb + ((t == 2) ? O_VTL : O_VTH);
#pragma unroll
            for (int kt = 0; kt < 9; kt++) {
                int kel = kt * 16 + qc;
                uint32_t af[4];
                af[0] = lds32(A + m * SKR + kel);
                af[1] = lds32(A + (m + 8) * SKR + kel);
                af[2] = lds32(A + m * SKR + kel + 8);
                af[3] = lds32(A + (m + 8) * SKR + kel + 8);
#pragma unroll
                for (int nt = 0; nt < 16; nt++) {
                    int n = nt * 8 + qr;
                    uint32_t b0 = lds32(B + n * SKR + kel);
                    uint32_t b1 = lds32(B + n * SKR + kel + 8);
                    mma16816(acc2[nt], af, b0, b1);
                }
            }
        }

        // epilogue: h = u * attn, split-store
#pragma unroll
        for (int nt = 0; nt < 16; nt++) {
            int col = e0 + nt * 8 + qc;
#pragma unroll
            for (int p = 0; p < 2; p++) {
                int i = m + p * 8;
                if (i < TT) {
                    float2 u2 = *(const float2*)(uvb + (size_t)i * NUV + col);
                    float h0 = acc2[nt][2*p]     * u2.x;
                    float h1 = acc2[nt][2*p + 1] * u2.y;
                    __nv_bfloat16 hh0, hl0, hh1, hl1;
                    split1(h0, hh0, hl0); split1(h1, hh1, hl1);
                    size_t ro = (size_t)(b * TT + i) * EE + col;
                    *(__nv_bfloat162*)(g_hh + ro) = __nv_bfloat162(hh0, hh1);
                    *(__nv_bfloat162*)(g_hl + ro) = __nv_bfloat162(hl0, hl1);
                }
            }
        }
        __syncthreads();   // before overwriting vt next chunk
    }
}

// ---------------- launch ----------------------------------------------------
extern "C" void kernel_launch(void* const* d_in, const int* in_sizes, int n_in,
                              void* d_out, int out_size) {
    (void)in_sizes; (void)n_in; (void)out_size;
    const float* x     = (const float*)d_in[0];
    const float* W_uv  = (const float*)d_in[1];
    const float* W_o   = (const float*)d_in[2];
    const float* gamma = (const float*)d_in[3];
    const float* beta  = (const float*)d_in[4];
    const float* g     = (const float*)d_in[5];
    const float* res   = (const float*)d_in[6];
    float* out = (float*)d_out;

    cudaFuncSetAttribute(k_attn2, cudaFuncAttributeMaxDynamicSharedMemorySize,
                         AT_SMEM_BYTES);

    k_rnorm<<<MTOT / 8, dim3(32, 8)>>>(x, g);
    k_split_x<<<MTOT * 64 / 256, 256>>>(x);
    k_split_w<<<(NUV * 64 + DD * 128 + 255) / 256, 256>>>(W_uv, W_o);
    k_gemm_mma<0><<<dim3(NUV / 128, MTOT / 128), 256>>>(nullptr, nullptr, nullptr);
    k_attn2<<<BATCH, 288, AT_SMEM_BYTES>>>(gamma, beta);
    k_gemm_mma<1><<<dim3(DD / 128, MTOT / 128), 256>>>(x, res, out);
}

// round 7
// speedup vs baseline: 1.4931x; 1.3171x over previous
#include <cuda_runtime.h>
#include <cuda_bf16.h>
#include <cstdint>

#define BATCH 1024
#define TT    133
#define DD    256
#define EE    512
#define SS    128
#define NUV   1152
#define MTOT  (BATCH*TT)     // 136192
#define INV_SQRT_S 0.08838834764831845f
#define EPSV  1e-5f

typedef unsigned long long ull;

// ---------------- scratch ----------------------------------------------------
__device__ float g_rn[MTOT];
__device__ float g_uv[(size_t)MTOT * NUV];
__device__ __align__(16) __nv_bfloat16 g_xh[(size_t)MTOT * DD];
__device__ __align__(16) __nv_bfloat16 g_xl[(size_t)MTOT * DD];
__device__ __align__(16) __nv_bfloat16 g_wh[(size_t)NUV * DD];
__device__ __align__(16) __nv_bfloat16 g_wl[(size_t)NUV * DD];
__device__ __align__(16) __nv_bfloat16 g_woh[(size_t)DD * EE];
__device__ __align__(16) __nv_bfloat16 g_wol[(size_t)DD * EE];
__device__ __align__(16) __nv_bfloat16 g_hh[(size_t)MTOT * EE];
__device__ __align__(16) __nv_bfloat16 g_hl[(size_t)MTOT * EE];

// ---------------- helpers ----------------------------------------------------
__device__ __forceinline__ uint32_t smem_u32(const void* p) {
    uint32_t a;
    asm("{ .reg .u64 t; cvta.to.shared.u64 t, %1; cvt.u32.u64 %0, t; }"
        : "=r"(a) : "l"(p));
    return a;
}
__device__ __forceinline__ float silu_f(float v) { return v / (1.0f + __expf(-v)); }
__device__ __forceinline__ void split1(float v, __nv_bfloat16 &h, __nv_bfloat16 &l) {
    h = __float2bfloat16(v);
    l = __float2bfloat16(v - __bfloat162float(h));
}
__device__ __forceinline__ void mma16816(float (&d)[4], const uint32_t (&a)[4],
                                         uint32_t b0, uint32_t b1) {
    asm volatile("mma.sync.aligned.m16n8k16.row.col.f32.bf16.bf16.f32 "
                 "{%0,%1,%2,%3}, {%4,%5,%6,%7}, {%8,%9}, {%0,%1,%2,%3};"
                 : "+f"(d[0]), "+f"(d[1]), "+f"(d[2]), "+f"(d[3])
                 : "r"(a[0]), "r"(a[1]), "r"(a[2]), "r"(a[3]), "r"(b0), "r"(b1));
}
__device__ __forceinline__ void ldmx4(uint32_t (&r)[4], uint32_t addr) {
    asm volatile("ldmatrix.sync.aligned.m8n8.x4.shared.b16 {%0,%1,%2,%3}, [%4];"
                 : "=r"(r[0]), "=r"(r[1]), "=r"(r[2]), "=r"(r[3]) : "r"(addr));
}
__device__ __forceinline__ uint32_t lds32(const __nv_bfloat16* p) {
    return *(const uint32_t*)p;
}
#define CP_ASYNC16(s, g) \
    asm volatile("cp.async.cg.shared.global [%0], [%1], 16;" :: "r"(s), "l"(g))
#define CP_COMMIT() asm volatile("cp.async.commit_group;")
#define CP_WAIT1()  asm volatile("cp.async.wait_group 1;")

// ---------------- fused rnorm + x split --------------------------------------
__global__ void k_rnorm_split(const float* __restrict__ x, const float* __restrict__ g) {
    int row = blockIdx.x * 8 + threadIdx.y;
    int lane = threadIdx.x;
    const float4* xr = (const float4*)(x + (size_t)row * DD);
    float4 v0 = xr[lane], v1 = xr[lane + 32];
    float s = v0.x*v0.x + v0.y*v0.y + v0.z*v0.z + v0.w*v0.w
            + v1.x*v1.x + v1.y*v1.y + v1.z*v1.z + v1.w*v1.w;
#pragma unroll
    for (int o = 16; o; o >>= 1) s += __shfl_xor_sync(0xffffffffu, s, o);
    float sc = g[0] / fmaxf(sqrtf(s) * 0.0625f, EPSV);
    size_t base = (size_t)row * 64;        // float4 index
#pragma unroll
    for (int half = 0; half < 2; half++) {
        float4 v = half ? v1 : v0;
        size_t idx = base + lane + half * 32;
        __nv_bfloat16 h0,h1,h2,h3,l0,l1,l2,l3;
        split1(v.x*sc,h0,l0); split1(v.y*sc,h1,l1);
        split1(v.z*sc,h2,l2); split1(v.w*sc,h3,l3);
        __nv_bfloat162* dh = (__nv_bfloat162*)(g_xh + idx*4);
        __nv_bfloat162* dl = (__nv_bfloat162*)(g_xl + idx*4);
        dh[0] = __nv_bfloat162(h0,h1); dh[1] = __nv_bfloat162(h2,h3);
        dl[0] = __nv_bfloat162(l0,l1); dl[1] = __nv_bfloat162(l2,l3);
    }
}

// ---------------- weight split ------------------------------------------------
__global__ void k_split_w(const float* __restrict__ Wuv, const float* __restrict__ Wo) {
    int idx = blockIdx.x * 256 + threadIdx.x;
    const int N1 = NUV * DD / 4;
    const int N2 = DD * EE / 4;
    if (idx < N1) {
        float4 v = ((const float4*)Wuv)[idx];
        __nv_bfloat16 h0,h1,h2,h3,l0,l1,l2,l3;
        split1(v.x,h0,l0); split1(v.y,h1,l1); split1(v.z,h2,l2); split1(v.w,h3,l3);
        __nv_bfloat162* ph = (__nv_bfloat162*)(g_wh + (size_t)idx*4);
        __nv_bfloat162* pl = (__nv_bfloat162*)(g_wl + (size_t)idx*4);
        ph[0] = __nv_bfloat162(h0,h1); ph[1] = __nv_bfloat162(h2,h3);
        pl[0] = __nv_bfloat162(l0,l1); pl[1] = __nv_bfloat162(l2,l3);
    } else if (idx < N1 + N2) {
        int j = idx - N1;
        float4 v = ((const float4*)Wo)[j];
        __nv_bfloat16 h0,h1,h2,h3,l0,l1,l2,l3;
        split1(v.x,h0,l0); split1(v.y,h1,l1); split1(v.z,h2,l2); split1(v.w,h3,l3);
        __nv_bfloat162* ph = (__nv_bfloat162*)(g_woh + (size_t)j*4);
        __nv_bfloat162* pl = (__nv_bfloat162*)(g_wol + (size_t)j*4);
        ph[0] = __nv_bfloat162(h0,h1); ph[1] = __nv_bfloat162(h2,h3);
        pl[0] = __nv_bfloat162(l0,l1); pl[1] = __nv_bfloat162(l2,l3);
    }
}

// ---------------- mma.sync bf16-split GEMM: ldmatrix + cp.async 3-stage ------
// GEMM==0: g_uv = silu([xh|xl] @ [wh|wl]^T), K=256, N=1152
// GEMM==1: out  = [hh|hl] @ [woh|wol]^T + x*res, K=512, N=256
// CTA 128x128, 8 warps 64x32; padded row stride 40 bf16 (80 B) — ldmatrix's
// 8 rows x 16B pattern covers all 32 banks exactly once (verified).
#define STRIDE   40
#define STG_B    10240                 // one 128x32 tile in bytes (128*40*2)
#define GM_SMEM  (6 * STG_B)           // 3 stages x (A+B) = 61440 bytes

template<int GEMM>
__global__ __launch_bounds__(256, 2)
void k_gemm_mma(const float* __restrict__ x, const float* __restrict__ res,
                float* __restrict__ outp_param) {
    constexpr int KREAL = (GEMM == 0) ? 256 : 512;
    constexpr int LDC   = (GEMM == 0) ? NUV : DD;
    constexpr int KC    = KREAL / 32;
    constexpr int NC    = 3 * KC;
    const __nv_bfloat16* Ah = (GEMM == 0) ? g_xh : g_hh;
    const __nv_bfloat16* Al = (GEMM == 0) ? g_xl : g_hl;
    const __nv_bfloat16* Bh = (GEMM == 0) ? g_wh : g_woh;
    const __nv_bfloat16* Bl = (GEMM == 0) ? g_wl : g_wol;
    float* outp = (GEMM == 0) ? g_uv : outp_param;   // device-side symbol ref!

    extern __shared__ __align__(16) char smc[];
    uint32_t sbase = smem_u32(smc);                  // A stages at st*STG_B
    uint32_t sbB   = sbase + 3 * STG_B;              // B stages

    int tid = threadIdx.x, lane = tid & 31, wid = tid >> 5;
    int m0 = blockIdx.y * 128, n0 = blockIdx.x * 128;
    int wm = (wid & 1) * 64, wn = (wid >> 1) * 32;
    int qr = lane >> 2, qc = (lane & 3) * 2;

    // loader per-thread: 2 x 16B chunks for A and B each
    int lrow = (tid * 2) >> 2;          // tid/2
    int lu   = (tid * 2) & 3;           // (2*tid)%4 -> 0 or 2
    uint32_t soff0 = lrow * 80 + lu * 16;
    uint32_t soff1 = lrow * 80 + (lu + 1) * 16;

    // ldmatrix lane bases (byte offsets within a stage)
    uint32_t aoff = (uint32_t)((wm + (lane & 7) + ((lane >> 3) & 1) * 8) * 80
                               + ((lane >> 4) & 1) * 16);
    uint32_t boff = (uint32_t)((wn + ((lane >> 4) & 1) * 16 + (lane & 7)
                               + 0) * 80 + (((lane >> 3) & 1) * 16));
    // B x4 mapping: lanes 0-7 -> rows wn+0-7 (k lo), 8-15 -> same rows (k hi),
    // 16-23 -> rows wn+8-15 (k lo), 24-31 -> rows wn+8-15 (k hi)
    boff = (uint32_t)((wn + ((lane >> 4) & 1) * 8 + (lane & 7)) * 80
                      + ((lane >> 3) & 1) * 16);

    float acc[4][4][4];
#pragma unroll
    for (int i = 0; i < 4; i++)
#pragma unroll
        for (int j = 0; j < 4; j++)
#pragma unroll
            for (int k = 0; k < 4; k++) acc[i][j][k] = 0.f;

#define G_ISSUE(c) do { \
    int st_ = (c) % 3; \
    int term = (c) / KC; \
    int kk = ((c) % KC) * 32; \
    const __nv_bfloat16* a_ = (term == 1) ? Al : Ah; \
    const __nv_bfloat16* b_ = (term == 2) ? Bl : Bh; \
    uint32_t sa_ = sbase + st_ * STG_B; \
    uint32_t sb_ = sbB   + st_ * STG_B; \
    CP_ASYNC16(sa_ + soff0, a_ + (size_t)(m0 + lrow) * KREAL + kk + lu * 8); \
    CP_ASYNC16(sa_ + soff1, a_ + (size_t)(m0 + lrow) * KREAL + kk + (lu + 1) * 8); \
    CP_ASYNC16(sb_ + soff0, b_ + (size_t)(n0 + lrow) * KREAL + kk + lu * 8); \
    CP_ASYNC16(sb_ + soff1, b_ + (size_t)(n0 + lrow) * KREAL + kk + (lu + 1) * 8); \
} while (0)

    G_ISSUE(0); CP_COMMIT();
    G_ISSUE(1); CP_COMMIT();

    for (int c = 0; c < NC; c++) {
        int st = c % 3;
        CP_WAIT1();
        __syncthreads();
        uint32_t sa_st = sbase + st * STG_B;
        uint32_t sb_st = sbB   + st * STG_B;
#pragma unroll
        for (int ks = 0; ks < 2; ks++) {
            uint32_t kof = ks * 32;     // 16 elements = 32 bytes
            uint32_t b01[4], b23[4];
            ldmx4(b01, sb_st + boff + kof);              // nt 0,1
            ldmx4(b23, sb_st + boff + 16 * 80 + kof);    // nt 2,3
#pragma unroll
            for (int mt = 0; mt < 4; mt++) {
                uint32_t af[4];
                ldmx4(af, sa_st + aoff + mt * 16 * 80 + kof);
                mma16816(acc[mt][0], af, b01[0], b01[1]);
                mma16816(acc[mt][1], af, b01[2], b01[3]);
                mma16816(acc[mt][2], af, b23[0], b23[1]);
                mma16816(acc[mt][3], af, b23[2], b23[3]);
            }
        }
        if (c + 2 < NC) G_ISSUE(c + 2);
        CP_COMMIT();
    }
#undef G_ISSUE

#pragma unroll
    for (int mt = 0; mt < 4; mt++) {
#pragma unroll
        for (int nt = 0; nt < 4; nt++) {
            int gm = m0 + wm + mt * 16 + qr;
            int gn = n0 + wn + nt * 8 + qc;
            float* d = acc[mt][nt];
            if (GEMM == 0) {
                float2 o0 = make_float2(silu_f(d[0]), silu_f(d[1]));
                float2 o1 = make_float2(silu_f(d[2]), silu_f(d[3]));
                *(float2*)(outp + (size_t)gm * LDC + gn) = o0;
                *(float2*)(outp + (size_t)(gm + 8) * LDC + gn) = o1;
            } else {
                float2 xa0 = *(const float2*)(x + (size_t)gm * DD + gn);
                float2 xa1 = *(const float2*)(x + (size_t)(gm + 8) * DD + gn);
                float2 rr  = *(const float2*)(res + gn);
                float2 o0 = make_float2(d[0] + xa0.x * rr.x, d[1] + xa0.y * rr.y);
                float2 o1 = make_float2(d[2] + xa1.x * rr.x, d[3] + xa1.y * rr.y);
                *(float2*)(outp + (size_t)gm * LDC + gn) = o0;
                *(float2*)(outp + (size_t)(gm + 8) * LDC + gn) = o1;
            }
        }
    }
}

// ---------------- attention v2 (unchanged from round 6) ----------------------
#define O_QH   0
#define O_QL   19584
#define O_KH   39168
#define O_KL   58752
#define O_KERH 0
#define O_KERL 21888
#define O_VTH  43776
#define O_VTL  63232
#define AT_SMEM_BYTES (82688 * 2)
#define SQK 136
#define SKR 152

__global__ __launch_bounds__(288, 1)
void k_attn2(const float* __restrict__ gamma, const float* __restrict__ beta) {
    extern __shared__ __align__(16) __nv_bfloat16 sb[];
    int b = blockIdx.x, tid = threadIdx.x;
    int w = tid >> 5, lane = tid & 31;
    int qr = lane >> 2, qc = (lane & 3) * 2;
    const float* uvb = g_uv + (size_t)b * TT * NUV;

    for (int idx = tid; idx < 144 * 32; idx += 288) {
        int i = idx >> 5, s4 = (idx & 31) * 4;
        bool valid = (i < TT);
        float4 base = valid ? *(const float4*)(uvb + (size_t)i * NUV + 2*EE + s4)
                            : make_float4(0.f, 0.f, 0.f, 0.f);
        float4 ga = *(const float4*)(gamma + s4);
        float4 gk = *(const float4*)(gamma + SS + s4);
        float4 ba = *(const float4*)(beta + s4);
        float4 bk = *(const float4*)(beta + SS + s4);
        float q[4], k[4];
        q[0] = valid ? fmaf(base.x, ga.x, ba.x) : 0.f;
        q[1] = valid ? fmaf(base.y, ga.y, ba.y) : 0.f;
        q[2] = valid ? fmaf(base.z, ga.z, ba.z) : 0.f;
        q[3] = valid ? fmaf(base.w, ga.w, ba.w) : 0.f;
        k[0] = valid ? fmaf(base.x, gk.x, bk.x) : 0.f;
        k[1] = valid ? fmaf(base.y, gk.y, bk.y) : 0.f;
        k[2] = valid ? fmaf(base.z, gk.z, bk.z) : 0.f;
        k[3] = valid ? fmaf(base.w, gk.w, bk.w) : 0.f;
        __nv_bfloat16 qh[4], ql[4], kh[4], kl[4];
#pragma unroll
        for (int t = 0; t < 4; t++) { split1(q[t], qh[t], ql[t]); split1(k[t], kh[t], kl[t]); }
        int off = i * SQK + s4;
        *(__nv_bfloat162*)(sb + O_QH + off)     = __nv_bfloat162(qh[0], qh[1]);
        *(__nv_bfloat162*)(sb + O_QH + off + 2) = __nv_bfloat162(qh[2], qh[3]);
        *(__nv_bfloat162*)(sb + O_QL + off)     = __nv_bfloat162(ql[0], ql[1]);
        *(__nv_bfloat162*)(sb + O_QL + off + 2) = __nv_bfloat162(ql[2], ql[3]);
        *(__nv_bfloat162*)(sb + O_KH + off)     = __nv_bfloat162(kh[0], kh[1]);
        *(__nv_bfloat162*)(sb + O_KH + off + 2) = __nv_bfloat162(kh[2], kh[3]);
        *(__nv_bfloat162*)(sb + O_KL + off)     = __nv_bfloat162(kl[0], kl[1]);
        *(__nv_bfloat162*)(sb + O_KL + off + 2) = __nv_bfloat162(kl[2], kl[3]);
    }
    __syncthreads();

    float acc[17][4];
#pragma unroll
    for (int nt = 0; nt < 17; nt++)
#pragma unroll
        for (int t = 0; t < 4; t++) acc[nt][t] = 0.f;

    int m = w * 16 + qr;
#pragma unroll
    for (int t = 0; t < 3; t++) {
        const __nv_bfloat16* A = sb + ((t == 1) ? O_QL : O_QH);
        const __nv_bfloat16* B = sb + ((t == 2) ? O_KL : O_KH);
#pragma unroll
        for (int ks = 0; ks < 8; ks++) {
            int kel = ks * 16 + qc;
            uint32_t af[4];
            af[0] = lds32(A + m * SQK + kel);
            af[1] = lds32(A + (m + 8) * SQK + kel);
            af[2] = lds32(A + m * SQK + kel + 8);
            af[3] = lds32(A + (m + 8) * SQK + kel + 8);
#pragma unroll
            for (int nt = 0; nt < 17; nt++) {
                int n = nt * 8 + qr;
                uint32_t b0 = lds32(B + n * SQK + kel);
                uint32_t b1 = lds32(B + n * SQK + kel + 8);
                mma16816(acc[nt], af, b0, b1);
            }
        }
    }
    __syncthreads();

#pragma unroll
    for (int nt = 0; nt < 17; nt++) {
        int col = nt * 8 + qc;
#pragma unroll
        for (int p = 0; p < 2; p++) {
            int row = m + p * 8;
            float v0 = fmaxf(acc[nt][2*p]     * INV_SQRT_S, 0.f);
            float v1 = fmaxf(acc[nt][2*p + 1] * INV_SQRT_S, 0.f);
            v0 *= v0; v1 *= v1;
            __nv_bfloat16 h0, l0, h1, l1;
            split1(v0, h0, l0); split1(v1, h1, l1);
            *(__nv_bfloat162*)(sb + O_KERH + row * SKR + col) = __nv_bfloat162(h0, h1);
            *(__nv_bfloat162*)(sb + O_KERL + row * SKR + col) = __nv_bfloat162(l0, l1);
        }
    }
    for (int idx = tid; idx < 144 * 4; idx += 288) {
        int row = idx >> 2, c = 136 + (idx & 3) * 2;
        *(__nv_bfloat162*)(sb + O_KERH + row * SKR + c) = __nv_bfloat162(__nv_bfloat16(0.f), __nv_bfloat16(0.f));
        *(__nv_bfloat162*)(sb + O_KERL + row * SKR + c) = __nv_bfloat162(__nv_bfloat16(0.f), __nv_bfloat16(0.f));
    }
    __syncthreads();

    for (int ch = 0; ch < 4; ch++) {
        int e0 = ch * 128;
        for (int idx = tid; idx < 144 * 32; idx += 288) {
            int j = idx >> 5, e4 = (idx & 31) * 4;
            float4 v = (j < TT) ? *(const float4*)(uvb + (size_t)j * NUV + EE + e0 + e4)
                                : make_float4(0.f, 0.f, 0.f, 0.f);
            float vv[4] = {v.x, v.y, v.z, v.w};
#pragma unroll
            for (int t = 0; t < 4; t++) {
                __nv_bfloat16 h, l;
                split1(vv[t], h, l);
                sb[O_VTH + (e4 + t) * SKR + j] = h;
                sb[O_VTL + (e4 + t) * SKR + j] = l;
            }
        }
        __syncthreads();

        float acc2[16][4];
#pragma unroll
        for (int nt = 0; nt < 16; nt++)
#pragma unroll
            for (int t = 0; t < 4; t++) acc2[nt][t] = 0.f;

#pragma unroll
        for (int t = 0; t < 3; t++) {
            const __nv_bfloat16* A = sb + ((t == 1) ? O_KERL : O_KERH);
            const __nv_bfloat16* B = sb + ((t == 2) ? O_VTL : O_VTH);
#pragma unroll
            for (int kt = 0; kt < 9; kt++) {
                int kel = kt * 16 + qc;
                uint32_t af[4];
                af[0] = lds32(A + m * SKR + kel);
                af[1] = lds32(A + (m + 8) * SKR + kel);
                af[2] = lds32(A + m * SKR + kel + 8);
                af[3] = lds32(A + (m + 8) * SKR + kel + 8);
#pragma unroll
                for (int nt = 0; nt < 16; nt++) {
                    int n = nt * 8 + qr;
                    uint32_t b0 = lds32(B + n * SKR + kel);
                    uint32_t b1 = lds32(B + n * SKR + kel + 8);
                    mma16816(acc2[nt], af, b0, b1);
                }
            }
        }

#pragma unroll
        for (int nt = 0; nt < 16; nt++) {
            int col = e0 + nt * 8 + qc;
#pragma unroll
            for (int p = 0; p < 2; p++) {
                int i = m + p * 8;
                if (i < TT) {
                    float2 u2 = *(const float2*)(uvb + (size_t)i * NUV + col);
                    float h0 = acc2[nt][2*p]     * u2.x;
                    float h1 = acc2[nt][2*p + 1] * u2.y;
                    __nv_bfloat16 hh0, hl0, hh1, hl1;
                    split1(h0, hh0, hl0); split1(h1, hh1, hl1);
                    size_t ro = (size_t)(b * TT + i) * EE + col;
                    *(__nv_bfloat162*)(g_hh + ro) = __nv_bfloat162(hh0, hh1);
                    *(__nv_bfloat162*)(g_hl + ro) = __nv_bfloat162(hl0, hl1);
                }
            }
        }
        __syncthreads();
    }
}

// ---------------- launch ----------------------------------------------------
extern "C" void kernel_launch(void* const* d_in, const int* in_sizes, int n_in,
                              void* d_out, int out_size) {
    (void)in_sizes; (void)n_in; (void)out_size;
    const float* x     = (const float*)d_in[0];
    const float* W_uv  = (const float*)d_in[1];
    const float* W_o   = (const float*)d_in[2];
    const float* gamma = (const float*)d_in[3];
    const float* beta  = (const float*)d_in[4];
    const float* g     = (const float*)d_in[5];
    const float* res   = (const float*)d_in[6];
    float* out = (float*)d_out;

    cudaFuncSetAttribute(k_attn2, cudaFuncAttributeMaxDynamicSharedMemorySize,
                         AT_SMEM_BYTES);
    cudaFuncSetAttribute(k_gemm_mma<0>, cudaFuncAttributeMaxDynamicSharedMemorySize,
                         GM_SMEM);
    cudaFuncSetAttribute(k_gemm_mma<1>, cudaFuncAttributeMaxDynamicSharedMemorySize,
                         GM_SMEM);

    k_rnorm_split<<<MTOT / 8, dim3(32, 8)>>>(x, g);
    k_split_w<<<(NUV * 64 + DD * 128 + 255) / 256, 256>>>(W_uv, W_o);
    k_gemm_mma<0><<<dim3(NUV / 128, MTOT / 128), 256, GM_SMEM>>>(nullptr, nullptr, nullptr);
    k_attn2<<<BATCH, 288, AT_SMEM_BYTES>>>(gamma, beta);
    k_gemm_mma<1><<<dim3(DD / 128, MTOT / 128), 256, GM_SMEM>>>(x, res, out);
}

// round 9
// speedup vs baseline: 1.5180x; 1.0167x over previous
#include <cuda_runtime.h>
#include <cuda_bf16.h>
#include <cstdint>

#define BATCH 1024
#define TT    133
#define DD    256
#define EE    512
#define SS    128
#define NUV   1152
#define MTOT  (BATCH*TT)     // 136192
#define INV_SQRT_S 0.08838834764831845f
#define EPSV  1e-5f

typedef unsigned long long ull;

// ---------------- scratch ----------------------------------------------------
__device__ float g_uv[(size_t)MTOT * NUV];
__device__ __align__(16) __nv_bfloat16 g_xh[(size_t)MTOT * DD];
__device__ __align__(16) __nv_bfloat16 g_xl[(size_t)MTOT * DD];
__device__ __align__(16) __nv_bfloat16 g_wh[(size_t)NUV * DD];
__device__ __align__(16) __nv_bfloat16 g_wl[(size_t)NUV * DD];
__device__ __align__(16) __nv_bfloat16 g_woh[(size_t)DD * EE];
__device__ __align__(16) __nv_bfloat16 g_wol[(size_t)DD * EE];
__device__ __align__(16) __nv_bfloat16 g_hh[(size_t)MTOT * EE];
__device__ __align__(16) __nv_bfloat16 g_hl[(size_t)MTOT * EE];

// ---------------- helpers ----------------------------------------------------
__device__ __forceinline__ uint32_t smem_u32(const void* p) {
    uint32_t a;
    asm("{ .reg .u64 t; cvta.to.shared.u64 t, %1; cvt.u32.u64 %0, t; }"
        : "=r"(a) : "l"(p));
    return a;
}
__device__ __forceinline__ float silu_f(float v) { return v / (1.0f + __expf(-v)); }
__device__ __forceinline__ void split1(float v, __nv_bfloat16 &h, __nv_bfloat16 &l) {
    h = __float2bfloat16(v);
    l = __float2bfloat16(v - __bfloat162float(h));
}
__device__ __forceinline__ void mma16816(float (&d)[4], const uint32_t (&a)[4],
                                         uint32_t b0, uint32_t b1) {
    asm volatile("mma.sync.aligned.m16n8k16.row.col.f32.bf16.bf16.f32 "
                 "{%0,%1,%2,%3}, {%4,%5,%6,%7}, {%8,%9}, {%0,%1,%2,%3};"
                 : "+f"(d[0]), "+f"(d[1]), "+f"(d[2]), "+f"(d[3])
                 : "r"(a[0]), "r"(a[1]), "r"(a[2]), "r"(a[3]), "r"(b0), "r"(b1));
}
__device__ __forceinline__ void ldmx4(uint32_t (&r)[4], uint32_t addr) {
    asm volatile("ldmatrix.sync.aligned.m8n8.x4.shared.b16 {%0,%1,%2,%3}, [%4];"
                 : "=r"(r[0]), "=r"(r[1]), "=r"(r[2]), "=r"(r[3]) : "r"(addr));
}
#define CP_ASYNC16(s, g) \
    asm volatile("cp.async.cg.shared.global [%0], [%1], 16;" :: "r"(s), "l"(g))
#define CP_COMMIT() asm volatile("cp.async.commit_group;")
#define CP_WAIT1()  asm volatile("cp.async.wait_group 1;")

// ---------------- fused rnorm + x split --------------------------------------
__global__ void k_rnorm_split(const float* __restrict__ x, const float* __restrict__ g) {
    int row = blockIdx.x * 8 + threadIdx.y;
    int lane = threadIdx.x;
    const float4* xr = (const float4*)(x + (size_t)row * DD);
    float4 v0 = xr[lane], v1 = xr[lane + 32];
    float s = v0.x*v0.x + v0.y*v0.y + v0.z*v0.z + v0.w*v0.w
            + v1.x*v1.x + v1.y*v1.y + v1.z*v1.z + v1.w*v1.w;
#pragma unroll
    for (int o = 16; o; o >>= 1) s += __shfl_xor_sync(0xffffffffu, s, o);
    float sc = g[0] / fmaxf(sqrtf(s) * 0.0625f, EPSV);
    size_t base = (size_t)row * 64;
#pragma unroll
    for (int half = 0; half < 2; half++) {
        float4 v = half ? v1 : v0;
        size_t idx = base + lane + half * 32;
        __nv_bfloat16 h0,h1,h2,h3,l0,l1,l2,l3;
        split1(v.x*sc,h0,l0); split1(v.y*sc,h1,l1);
        split1(v.z*sc,h2,l2); split1(v.w*sc,h3,l3);
        __nv_bfloat162* dh = (__nv_bfloat162*)(g_xh + idx*4);
        __nv_bfloat162* dl = (__nv_bfloat162*)(g_xl + idx*4);
        dh[0] = __nv_bfloat162(h0,h1); dh[1] = __nv_bfloat162(h2,h3);
        dl[0] = __nv_bfloat162(l0,l1); dl[1] = __nv_bfloat162(l2,l3);
    }
}

// ---------------- weight split ------------------------------------------------
__global__ void k_split_w(const float* __restrict__ Wuv, const float* __restrict__ Wo) {
    int idx = blockIdx.x * 256 + threadIdx.x;
    const int N1 = NUV * DD / 4;
    const int N2 = DD * EE / 4;
    if (idx < N1) {
        float4 v = ((const float4*)Wuv)[idx];
        __nv_bfloat16 h0,h1,h2,h3,l0,l1,l2,l3;
        split1(v.x,h0,l0); split1(v.y,h1,l1); split1(v.z,h2,l2); split1(v.w,h3,l3);
        __nv_bfloat162* ph = (__nv_bfloat162*)(g_wh + (size_t)idx*4);
        __nv_bfloat162* pl = (__nv_bfloat162*)(g_wl + (size_t)idx*4);
        ph[0] = __nv_bfloat162(h0,h1); ph[1] = __nv_bfloat162(h2,h3);
        pl[0] = __nv_bfloat162(l0,l1); pl[1] = __nv_bfloat162(l2,l3);
    } else if (idx < N1 + N2) {
        int j = idx - N1;
        float4 v = ((const float4*)Wo)[j];
        __nv_bfloat16 h0,h1,h2,h3,l0,l1,l2,l3;
        split1(v.x,h0,l0); split1(v.y,h1,l1); split1(v.z,h2,l2); split1(v.w,h3,l3);
        __nv_bfloat162* ph = (__nv_bfloat162*)(g_woh + (size_t)j*4);
        __nv_bfloat162* pl = (__nv_bfloat162*)(g_wol + (size_t)j*4);
        ph[0] = __nv_bfloat162(h0,h1); ph[1] = __nv_bfloat162(h2,h3);
        pl[0] = __nv_bfloat162(l0,l1); pl[1] = __nv_bfloat162(l2,l3);
    }
}

// ---------------- GEMMs (unchanged from round 7 — validated) -----------------
#define STRIDE   40
#define STG_B    10240
#define GM_SMEM  (6 * STG_B)

template<int GEMM>
__global__ __launch_bounds__(256, 2)
void k_gemm_mma(const float* __restrict__ x, const float* __restrict__ res,
                float* __restrict__ outp_param) {
    constexpr int KREAL = (GEMM == 0) ? 256 : 512;
    constexpr int LDC   = (GEMM == 0) ? NUV : DD;
    constexpr int KC    = KREAL / 32;
    constexpr int NC    = 3 * KC;
    const __nv_bfloat16* Ah = (GEMM == 0) ? g_xh : g_hh;
    const __nv_bfloat16* Al = (GEMM == 0) ? g_xl : g_hl;
    const __nv_bfloat16* Bh = (GEMM == 0) ? g_wh : g_woh;
    const __nv_bfloat16* Bl = (GEMM == 0) ? g_wl : g_wol;
    float* outp = (GEMM == 0) ? g_uv : outp_param;

    extern __shared__ __align__(16) char smc[];
    uint32_t sbase = smem_u32(smc);
    uint32_t sbB   = sbase + 3 * STG_B;

    int tid = threadIdx.x, lane = tid & 31, wid = tid >> 5;
    int m0 = blockIdx.y * 128, n0 = blockIdx.x * 128;
    int wm = (wid & 1) * 64, wn = (wid >> 1) * 32;
    int qr = lane >> 2, qc = (lane & 3) * 2;

    int lrow = (tid * 2) >> 2;
    int lu   = (tid * 2) & 3;
    uint32_t soff0 = lrow * 80 + lu * 16;
    uint32_t soff1 = lrow * 80 + (lu + 1) * 16;

    uint32_t aoff = (uint32_t)((wm + (lane & 7) + ((lane >> 3) & 1) * 8) * 80
                               + ((lane >> 4) & 1) * 16);
    uint32_t boff = (uint32_t)((wn + ((lane >> 4) & 1) * 8 + (lane & 7)) * 80
                      + ((lane >> 3) & 1) * 16);

    float acc[4][4][4];
#pragma unroll
    for (int i = 0; i < 4; i++)
#pragma unroll
        for (int j = 0; j < 4; j++)
#pragma unroll
            for (int k = 0; k < 4; k++) acc[i][j][k] = 0.f;

#define G_ISSUE(c) do { \
    int st_ = (c) % 3; \
    int term = (c) / KC; \
    int kk = ((c) % KC) * 32; \
    const __nv_bfloat16* a_ = (term == 1) ? Al : Ah; \
    const __nv_bfloat16* b_ = (term == 2) ? Bl : Bh; \
    uint32_t sa_ = sbase + st_ * STG_B; \
    uint32_t sb_ = sbB   + st_ * STG_B; \
    CP_ASYNC16(sa_ + soff0, a_ + (size_t)(m0 + lrow) * KREAL + kk + lu * 8); \
    CP_ASYNC16(sa_ + soff1, a_ + (size_t)(m0 + lrow) * KREAL + kk + (lu + 1) * 8); \
    CP_ASYNC16(sb_ + soff0, b_ + (size_t)(n0 + lrow) * KREAL + kk + lu * 8); \
    CP_ASYNC16(sb_ + soff1, b_ + (size_t)(n0 + lrow) * KREAL + kk + (lu + 1) * 8); \
} while (0)

    G_ISSUE(0); CP_COMMIT();
    G_ISSUE(1); CP_COMMIT();

    for (int c = 0; c < NC; c++) {
        int st = c % 3;
        CP_WAIT1();
        __syncthreads();
        uint32_t sa_st = sbase + st * STG_B;
        uint32_t sb_st = sbB   + st * STG_B;
#pragma unroll
        for (int ks = 0; ks < 2; ks++) {
            uint32_t kof = ks * 32;
            uint32_t b01[4], b23[4];
            ldmx4(b01, sb_st + boff + kof);
            ldmx4(b23, sb_st + boff + 16 * 80 + kof);
#pragma unroll
            for (int mt = 0; mt < 4; mt++) {
                uint32_t af[4];
                ldmx4(af, sa_st + aoff + mt * 16 * 80 + kof);
                mma16816(acc[mt][0], af, b01[0], b01[1]);
                mma16816(acc[mt][1], af, b01[2], b01[3]);
                mma16816(acc[mt][2], af, b23[0], b23[1]);
                mma16816(acc[mt][3], af, b23[2], b23[3]);
            }
        }
        if (c + 2 < NC) G_ISSUE(c + 2);
        CP_COMMIT();
    }
#undef G_ISSUE

#pragma unroll
    for (int mt = 0; mt < 4; mt++) {
#pragma unroll
        for (int nt = 0; nt < 4; nt++) {
            int gm = m0 + wm + mt * 16 + qr;
            int gn = n0 + wn + nt * 8 + qc;
            float* d = acc[mt][nt];
            if (GEMM == 0) {
                float2 o0 = make_float2(silu_f(d[0]), silu_f(d[1]));
                float2 o1 = make_float2(silu_f(d[2]), silu_f(d[3]));
                *(float2*)(outp + (size_t)gm * LDC + gn) = o0;
                *(float2*)(outp + (size_t)(gm + 8) * LDC + gn) = o1;
            } else {
                float2 xa0 = *(const float2*)(x + (size_t)gm * DD + gn);
                float2 xa1 = *(const float2*)(x + (size_t)(gm + 8) * DD + gn);
                float2 rr  = *(const float2*)(res + gn);
                float2 o0 = make_float2(d[0] + xa0.x * rr.x, d[1] + xa0.y * rr.y);
                float2 o1 = make_float2(d[2] + xa1.x * rr.x, d[3] + xa1.y * rr.y);
                *(float2*)(outp + (size_t)gm * LDC + gn) = o0;
                *(float2*)(outp + (size_t)(gm + 8) * LDC + gn) = o1;
            }
        }
    }
}

// ---------------- attention v3: 576 thr, warp-pairs, ldmatrix ----------------
// smem (bf16 elem offsets): qh[144][136]@0 ql@19584 kh@39168 kl@58752
// then kernh[144][152]@0 kernl@21888 vth[128][152]@43776 vtl@63232
#define O_QH   0
#define O_QL   19584
#define O_KH   39168
#define O_KL   58752
#define O_KERH 0
#define O_KERL 21888
#define O_VTH  43776
#define O_VTL  63232
#define AT_SMEM_BYTES (82688 * 2)
#define SQK 136
#define SKR 152
#define SQKB 272
#define SKRB 304

__global__ __launch_bounds__(576, 1)
void k_attn3(const float* __restrict__ gamma, const float* __restrict__ beta) {
    extern __shared__ __align__(16) __nv_bfloat16 sb[];
    uint32_t sbu = smem_u32(sb);
    int b = blockIdx.x, tid = threadIdx.x;
    int w = tid >> 5, lane = tid & 31;
    int w2 = w >> 1, half = w & 1;
    int qr = lane >> 2, qc = (lane & 3) * 2;
    int m = w2 * 16 + qr;
    const float* uvb = g_uv + (size_t)b * TT * NUV;

    // ldmatrix lane offsets (byte): A-frag rows of 16, B-pair rows of 16
    int lrow16 = (lane & 7) + ((lane >> 3) & 1) * 8;   // 0..15 row within group
    uint32_t aoffQ = (uint32_t)((w2 * 16 + ((lane & 7) | (((lane >> 3) & 1) << 3))) * SQKB
                                + ((lane >> 4) & 1) * 16);
    uint32_t boffQ = (uint32_t)((((lane >> 4) & 1) * 8 + (lane & 7)) * SQKB
                                + ((lane >> 3) & 1) * 16);
    uint32_t aoffR = (uint32_t)((w2 * 16 + ((lane & 7) | (((lane >> 3) & 1) << 3))) * SKRB
                                + ((lane >> 4) & 1) * 16);
    uint32_t boffR = (uint32_t)((((lane >> 4) & 1) * 8 + (lane & 7)) * SKRB
                                + ((lane >> 3) & 1) * 16);
    (void)lrow16;

    // ---- phase A: build q/k hi-lo, rows >= TT zeroed ----
    for (int idx = tid; idx < 144 * 32; idx += 576) {
        int i = idx >> 5, s4 = (idx & 31) * 4;
        bool valid = (i < TT);
        float4 base = valid ? *(const float4*)(uvb + (size_t)i * NUV + 2*EE + s4)
                            : make_float4(0.f, 0.f, 0.f, 0.f);
        float4 ga = *(const float4*)(gamma + s4);
        float4 gk = *(const float4*)(gamma + SS + s4);
        float4 ba = *(const float4*)(beta + s4);
        float4 bk = *(const float4*)(beta + SS + s4);
        float q[4], k[4];
        q[0] = valid ? fmaf(base.x, ga.x, ba.x) : 0.f;
        q[1] = valid ? fmaf(base.y, ga.y, ba.y) : 0.f;
        q[2] = valid ? fmaf(base.z, ga.z, ba.z) : 0.f;
        q[3] = valid ? fmaf(base.w, ga.w, ba.w) : 0.f;
        k[0] = valid ? fmaf(base.x, gk.x, bk.x) : 0.f;
        k[1] = valid ? fmaf(base.y, gk.y, bk.y) : 0.f;
        k[2] = valid ? fmaf(base.z, gk.z, bk.z) : 0.f;
        k[3] = valid ? fmaf(base.w, gk.w, bk.w) : 0.f;
        __nv_bfloat16 qh[4], ql[4], kh[4], kl[4];
#pragma unroll
        for (int t = 0; t < 4; t++) { split1(q[t], qh[t], ql[t]); split1(k[t], kh[t], kl[t]); }
        int off = i * SQK + s4;
        *(__nv_bfloat162*)(sb + O_QH + off)     = __nv_bfloat162(qh[0], qh[1]);
        *(__nv_bfloat162*)(sb + O_QH + off + 2) = __nv_bfloat162(qh[2], qh[3]);
        *(__nv_bfloat162*)(sb + O_QL + off)     = __nv_bfloat162(ql[0], ql[1]);
        *(__nv_bfloat162*)(sb + O_QL + off + 2) = __nv_bfloat162(ql[2], ql[3]);
        *(__nv_bfloat162*)(sb + O_KH + off)     = __nv_bfloat162(kh[0], kh[1]);
        *(__nv_bfloat162*)(sb + O_KH + off + 2) = __nv_bfloat162(kh[2], kh[3]);
        *(__nv_bfloat162*)(sb + O_KL + off)     = __nv_bfloat162(kl[0], kl[1]);
        *(__nv_bfloat162*)(sb + O_KL + off + 2) = __nv_bfloat162(kl[2], kl[3]);
    }
    __syncthreads();

    // ---- scores: warp-pair w2 owns rows [16*w2,16*w2+16); half picks tiles ---
    // half 0: pairs 0..3 (tiles 0..7); half 1: pairs 4..8 (tiles 8..17; tile 17
    //         = pad cols, computes exact zeros -> pad handled for free)
    const int np    = half ? 5 : 4;
    const int pbase = half ? 4 : 0;
    float acc[10][4];
#pragma unroll
    for (int i = 0; i < 10; i++)
#pragma unroll
        for (int t = 0; t < 4; t++) acc[i][t] = 0.f;

#pragma unroll
    for (int t = 0; t < 3; t++) {
        uint32_t Abase = sbu + ((t == 1) ? O_QL : O_QH) * 2;
        uint32_t Bbase = sbu + ((t == 2) ? O_KL : O_KH) * 2;
#pragma unroll
        for (int ks = 0; ks < 8; ks++) {
            uint32_t kof = ks * 32;
            uint32_t af[4];
            ldmx4(af, Abase + aoffQ + kof);
#pragma unroll
            for (int j = 0; j < 5; j++) {
                if (j < np) {
                    uint32_t bb[4];
                    ldmx4(bb, Bbase + boffQ + (uint32_t)(pbase + j) * 16 * SQKB + kof);
                    mma16816(acc[2*j],     af, bb[0], bb[1]);
                    mma16816(acc[2*j + 1], af, bb[2], bb[3]);
                }
            }
        }
    }
    __syncthreads();   // all reads of q/k complete before kern overwrites

    // ---- kern = relu(scores/sqrt(S))^2, split-store ----
#pragma unroll
    for (int j = 0; j < 5; j++) {
        if (j < np) {
#pragma unroll
            for (int s = 0; s < 2; s++) {
                int col = ((pbase + j) * 2 + s) * 8 + qc;
#pragma unroll
                for (int p = 0; p < 2; p++) {
                    int row = m + p * 8;
                    float v0 = fmaxf(acc[2*j + s][2*p]     * INV_SQRT_S, 0.f);
                    float v1 = fmaxf(acc[2*j + s][2*p + 1] * INV_SQRT_S, 0.f);
                    v0 *= v0; v1 *= v1;
                    __nv_bfloat16 h0, l0, h1, l1;
                    split1(v0, h0, l0); split1(v1, h1, l1);
                    *(__nv_bfloat162*)(sb + O_KERH + row * SKR + col) = __nv_bfloat162(h0, h1);
                    *(__nv_bfloat162*)(sb + O_KERL + row * SKR + col) = __nv_bfloat162(l0, l1);
                }
            }
        }
    }
    __syncthreads();

    // ---- attn chunks: half picks 8 of 16 e-tiles ----
    for (int ch = 0; ch < 4; ch++) {
        int e0 = ch * 128;
        for (int idx = tid; idx < 144 * 32; idx += 576) {
            int j = idx >> 5, e4 = (idx & 31) * 4;
            float4 v = (j < TT) ? *(const float4*)(uvb + (size_t)j * NUV + EE + e0 + e4)
                                : make_float4(0.f, 0.f, 0.f, 0.f);
            float vv[4] = {v.x, v.y, v.z, v.w};
#pragma unroll
            for (int t = 0; t < 4; t++) {
                __nv_bfloat16 h, l;
                split1(vv[t], h, l);
                sb[O_VTH + (e4 + t) * SKR + j] = h;
                sb[O_VTL + (e4 + t) * SKR + j] = l;
            }
        }
        __syncthreads();

        float acc2[8][4];
#pragma unroll
        for (int i = 0; i < 8; i++)
#pragma unroll
            for (int t = 0; t < 4; t++) acc2[i][t] = 0.f;

#pragma unroll
        for (int t = 0; t < 3; t++) {
            uint32_t Abase = sbu + ((t == 1) ? O_KERL : O_KERH) * 2;
            uint32_t Bbase = sbu + ((t == 2) ? O_VTL : O_VTH) * 2;
#pragma unroll
            for (int kt = 0; kt < 9; kt++) {
                uint32_t kof = kt * 32;
                uint32_t af[4];
                ldmx4(af, Abase + aoffR + kof);
#pragma unroll
                for (int j = 0; j < 4; j++) {
                    uint32_t bb[4];
                    ldmx4(bb, Bbase + boffR + (uint32_t)(4 * half + j) * 16 * SKRB + kof);
                    mma16816(acc2[2*j],     af, bb[0], bb[1]);
                    mma16816(acc2[2*j + 1], af, bb[2], bb[3]);
                }
            }
        }

        // epilogue: h = u * attn, split-store
#pragma unroll
        for (int j = 0; j < 4; j++) {
#pragma unroll
            for (int s = 0; s < 2; s++) {
                int col = e0 + ((4 * half + j) * 2 + s) * 8 + qc;
#pragma unroll
                for (int p = 0; p < 2; p++) {
                    int i = m + p * 8;
                    if (i < TT) {
                        float2 u2 = *(const float2*)(uvb + (size_t)i * NUV + col);
                        float h0 = acc2[2*j + s][2*p]     * u2.x;
                        float h1 = acc2[2*j + s][2*p + 1] * u2.y;
                        __nv_bfloat16 hh0, hl0, hh1, hl1;
                        split1(h0, hh0, hl0); split1(h1, hh1, hl1);
                        size_t ro = (size_t)(b * TT + i) * EE + col;
                        *(__nv_bfloat162*)(g_hh + ro) = __nv_bfloat162(hh0, hh1);
                        *(__nv_bfloat162*)(g_hl + ro) = __nv_bfloat162(hl0, hl1);
                    }
                }
            }
        }
        __syncthreads();
    }
}

// ---------------- launch ----------------------------------------------------
extern "C" void kernel_launch(void* const* d_in, const int* in_sizes, int n_in,
                              void* d_out, int out_size) {
    (void)in_sizes; (void)n_in; (void)out_size;
    const float* x     = (const float*)d_in[0];
    const float* W_uv  = (const float*)d_in[1];
    const float* W_o   = (const float*)d_in[2];
    const float* gamma = (const float*)d_in[3];
    const float* beta  = (const float*)d_in[4];
    const float* g     = (const float*)d_in[5];
    const float* res   = (const float*)d_in[6];
    float* out = (float*)d_out;

    cudaFuncSetAttribute(k_attn3, cudaFuncAttributeMaxDynamicSharedMemorySize,
                         AT_SMEM_BYTES);
    cudaFuncSetAttribute(k_gemm_mma<0>, cudaFuncAttributeMaxDynamicSharedMemorySize,
                         GM_SMEM);
    cudaFuncSetAttribute(k_gemm_mma<1>, cudaFuncAttributeMaxDynamicSharedMemorySize,
                         GM_SMEM);

    k_rnorm_split<<<MTOT / 8, dim3(32, 8)>>>(x, g);
    k_split_w<<<(NUV * 64 + DD * 128 + 255) / 256, 256>>>(W_uv, W_o);
    k_gemm_mma<0><<<dim3(NUV / 128, MTOT / 128), 256, GM_SMEM>>>(nullptr, nullptr, nullptr);
    k_attn3<<<BATCH, 576, AT_SMEM_BYTES>>>(gamma, beta);
    k_gemm_mma<1><<<dim3(DD / 128, MTOT / 128), 256, GM_SMEM>>>(x, res, out);
}

// round 10
// speedup vs baseline: 1.7235x; 1.1353x over previous
#include <cuda_runtime.h>
#include <cuda_bf16.h>
#include <cstdint>

#define BATCH 1024
#define TT    133
#define DD    256
#define EE    512
#define SS    128
#define NUV   1152
#define MTOT  (BATCH*TT)     // 136192
#define INV_SQRT_S 0.08838834764831845f
#define EPSV  1e-5f

typedef unsigned long long ull;

// ---------------- scratch ----------------------------------------------------
__device__ float g_uv[(size_t)MTOT * NUV];
__device__ __align__(16) __nv_bfloat16 g_xh[(size_t)MTOT * DD];
__device__ __align__(16) __nv_bfloat16 g_xl[(size_t)MTOT * DD];
__device__ __align__(16) __nv_bfloat16 g_wh[(size_t)NUV * DD];
__device__ __align__(16) __nv_bfloat16 g_wl[(size_t)NUV * DD];
__device__ __align__(16) __nv_bfloat16 g_woh[(size_t)DD * EE];
__device__ __align__(16) __nv_bfloat16 g_wol[(size_t)DD * EE];
__device__ __align__(16) __nv_bfloat16 g_hh[(size_t)MTOT * EE];
__device__ __align__(16) __nv_bfloat16 g_hl[(size_t)MTOT * EE];

// ---------------- helpers ----------------------------------------------------
__device__ __forceinline__ uint32_t smem_u32(const void* p) {
    uint32_t a;
    asm("{ .reg .u64 t; cvta.to.shared.u64 t, %1; cvt.u32.u64 %0, t; }"
        : "=r"(a) : "l"(p));
    return a;
}
__device__ __forceinline__ float silu_f(float v) { return v / (1.0f + __expf(-v)); }
__device__ __forceinline__ void split1(float v, __nv_bfloat16 &h, __nv_bfloat16 &l) {
    h = __float2bfloat16(v);
    l = __float2bfloat16(v - __bfloat162float(h));
}
__device__ __forceinline__ void mma16816(float (&d)[4], const uint32_t (&a)[4],
                                         uint32_t b0, uint32_t b1) {
    asm volatile("mma.sync.aligned.m16n8k16.row.col.f32.bf16.bf16.f32 "
                 "{%0,%1,%2,%3}, {%4,%5,%6,%7}, {%8,%9}, {%0,%1,%2,%3};"
                 : "+f"(d[0]), "+f"(d[1]), "+f"(d[2]), "+f"(d[3])
                 : "r"(a[0]), "r"(a[1]), "r"(a[2]), "r"(a[3]), "r"(b0), "r"(b1));
}
__device__ __forceinline__ void ldmx4(uint32_t (&r)[4], uint32_t addr) {
    asm volatile("ldmatrix.sync.aligned.m8n8.x4.shared.b16 {%0,%1,%2,%3}, [%4];"
                 : "=r"(r[0]), "=r"(r[1]), "=r"(r[2]), "=r"(r[3]) : "r"(addr));
}
__device__ __forceinline__ void ldmx4t(uint32_t (&r)[4], uint32_t addr) {
    asm volatile("ldmatrix.sync.aligned.m8n8.x4.trans.shared.b16 {%0,%1,%2,%3}, [%4];"
                 : "=r"(r[0]), "=r"(r[1]), "=r"(r[2]), "=r"(r[3]) : "r"(addr));
}
#define CP_ASYNC16(s, g) \
    asm volatile("cp.async.cg.shared.global [%0], [%1], 16;" :: "r"(s), "l"(g))
#define CP_COMMIT() asm volatile("cp.async.commit_group;")
#define CP_WAIT1()  asm volatile("cp.async.wait_group 1;")

// ---------------- fused rnorm + x split --------------------------------------
__global__ void k_rnorm_split(const float* __restrict__ x, const float* __restrict__ g) {
    int row = blockIdx.x * 8 + threadIdx.y;
    int lane = threadIdx.x;
    const float4* xr = (const float4*)(x + (size_t)row * DD);
    float4 v0 = xr[lane], v1 = xr[lane + 32];
    float s = v0.x*v0.x + v0.y*v0.y + v0.z*v0.z + v0.w*v0.w
            + v1.x*v1.x + v1.y*v1.y + v1.z*v1.z + v1.w*v1.w;
#pragma unroll
    for (int o = 16; o; o >>= 1) s += __shfl_xor_sync(0xffffffffu, s, o);
    float sc = g[0] / fmaxf(sqrtf(s) * 0.0625f, EPSV);
    size_t base = (size_t)row * 64;
#pragma unroll
    for (int half = 0; half < 2; half++) {
        float4 v = half ? v1 : v0;
        size_t idx = base + lane + half * 32;
        __nv_bfloat16 h0,h1,h2,h3,l0,l1,l2,l3;
        split1(v.x*sc,h0,l0); split1(v.y*sc,h1,l1);
        split1(v.z*sc,h2,l2); split1(v.w*sc,h3,l3);
        __nv_bfloat162* dh = (__nv_bfloat162*)(g_xh + idx*4);
        __nv_bfloat162* dl = (__nv_bfloat162*)(g_xl + idx*4);
        dh[0] = __nv_bfloat162(h0,h1); dh[1] = __nv_bfloat162(h2,h3);
        dl[0] = __nv_bfloat162(l0,l1); dl[1] = __nv_bfloat162(l2,l3);
    }
}

// ---------------- weight split ------------------------------------------------
__global__ void k_split_w(const float* __restrict__ Wuv, const float* __restrict__ Wo) {
    int idx = blockIdx.x * 256 + threadIdx.x;
    const int N1 = NUV * DD / 4;
    const int N2 = DD * EE / 4;
    if (idx < N1) {
        float4 v = ((const float4*)Wuv)[idx];
        __nv_bfloat16 h0,h1,h2,h3,l0,l1,l2,l3;
        split1(v.x,h0,l0); split1(v.y,h1,l1); split1(v.z,h2,l2); split1(v.w,h3,l3);
        __nv_bfloat162* ph = (__nv_bfloat162*)(g_wh + (size_t)idx*4);
        __nv_bfloat162* pl = (__nv_bfloat162*)(g_wl + (size_t)idx*4);
        ph[0] = __nv_bfloat162(h0,h1); ph[1] = __nv_bfloat162(h2,h3);
        pl[0] = __nv_bfloat162(l0,l1); pl[1] = __nv_bfloat162(l2,l3);
    } else if (idx < N1 + N2) {
        int j = idx - N1;
        float4 v = ((const float4*)Wo)[j];
        __nv_bfloat16 h0,h1,h2,h3,l0,l1,l2,l3;
        split1(v.x,h0,l0); split1(v.y,h1,l1); split1(v.z,h2,l2); split1(v.w,h3,l3);
        __nv_bfloat162* ph = (__nv_bfloat162*)(g_woh + (size_t)j*4);
        __nv_bfloat162* pl = (__nv_bfloat162*)(g_wol + (size_t)j*4);
        ph[0] = __nv_bfloat162(h0,h1); ph[1] = __nv_bfloat162(h2,h3);
        pl[0] = __nv_bfloat162(l0,l1); pl[1] = __nv_bfloat162(l2,l3);
    }
}

// ---------------- GEMMs (unchanged — validated) -------------------------------
#define STRIDE   40
#define STG_B    10240
#define GM_SMEM  (6 * STG_B)

template<int GEMM>
__global__ __launch_bounds__(256, 2)
void k_gemm_mma(const float* __restrict__ x, const float* __restrict__ res,
                float* __restrict__ outp_param) {
    constexpr int KREAL = (GEMM == 0) ? 256 : 512;
    constexpr int LDC   = (GEMM == 0) ? NUV : DD;
    constexpr int KC    = KREAL / 32;
    constexpr int NC    = 3 * KC;
    const __nv_bfloat16* Ah = (GEMM == 0) ? g_xh : g_hh;
    const __nv_bfloat16* Al = (GEMM == 0) ? g_xl : g_hl;
    const __nv_bfloat16* Bh = (GEMM == 0) ? g_wh : g_woh;
    const __nv_bfloat16* Bl = (GEMM == 0) ? g_wl : g_wol;
    float* outp = (GEMM == 0) ? g_uv : outp_param;

    extern __shared__ __align__(16) char smc[];
    uint32_t sbase = smem_u32(smc);
    uint32_t sbB   = sbase + 3 * STG_B;

    int tid = threadIdx.x, lane = tid & 31, wid = tid >> 5;
    int m0 = blockIdx.y * 128, n0 = blockIdx.x * 128;
    int wm = (wid & 1) * 64, wn = (wid >> 1) * 32;
    int qr = lane >> 2, qc = (lane & 3) * 2;

    int lrow = (tid * 2) >> 2;
    int lu   = (tid * 2) & 3;
    uint32_t soff0 = lrow * 80 + lu * 16;
    uint32_t soff1 = lrow * 80 + (lu + 1) * 16;

    uint32_t aoff = (uint32_t)((wm + (lane & 7) + ((lane >> 3) & 1) * 8) * 80
                               + ((lane >> 4) & 1) * 16);
    uint32_t boff = (uint32_t)((wn + ((lane >> 4) & 1) * 8 + (lane & 7)) * 80
                      + ((lane >> 3) & 1) * 16);

    float acc[4][4][4];
#pragma unroll
    for (int i = 0; i < 4; i++)
#pragma unroll
        for (int j = 0; j < 4; j++)
#pragma unroll
            for (int k = 0; k < 4; k++) acc[i][j][k] = 0.f;

#define G_ISSUE(c) do { \
    int st_ = (c) % 3; \
    int term = (c) / KC; \
    int kk = ((c) % KC) * 32; \
    const __nv_bfloat16* a_ = (term == 1) ? Al : Ah; \
    const __nv_bfloat16* b_ = (term == 2) ? Bl : Bh; \
    uint32_t sa_ = sbase + st_ * STG_B; \
    uint32_t sb_ = sbB   + st_ * STG_B; \
    CP_ASYNC16(sa_ + soff0, a_ + (size_t)(m0 + lrow) * KREAL + kk + lu * 8); \
    CP_ASYNC16(sa_ + soff1, a_ + (size_t)(m0 + lrow) * KREAL + kk + (lu + 1) * 8); \
    CP_ASYNC16(sb_ + soff0, b_ + (size_t)(n0 + lrow) * KREAL + kk + lu * 8); \
    CP_ASYNC16(sb_ + soff1, b_ + (size_t)(n0 + lrow) * KREAL + kk + (lu + 1) * 8); \
} while (0)

    G_ISSUE(0); CP_COMMIT();
    G_ISSUE(1); CP_COMMIT();

    for (int c = 0; c < NC; c++) {
        int st = c % 3;
        CP_WAIT1();
        __syncthreads();
        uint32_t sa_st = sbase + st * STG_B;
        uint32_t sb_st = sbB   + st * STG_B;
#pragma unroll
        for (int ks = 0; ks < 2; ks++) {
            uint32_t kof = ks * 32;
            uint32_t b01[4], b23[4];
            ldmx4(b01, sb_st + boff + kof);
            ldmx4(b23, sb_st + boff + 16 * 80 + kof);
#pragma unroll
            for (int mt = 0; mt < 4; mt++) {
                uint32_t af[4];
                ldmx4(af, sa_st + aoff + mt * 16 * 80 + kof);
                mma16816(acc[mt][0], af, b01[0], b01[1]);
                mma16816(acc[mt][1], af, b01[2], b01[3]);
                mma16816(acc[mt][2], af, b23[0], b23[1]);
                mma16816(acc[mt][3], af, b23[2], b23[3]);
            }
        }
        if (c + 2 < NC) G_ISSUE(c + 2);
        CP_COMMIT();
    }
#undef G_ISSUE

#pragma unroll
    for (int mt = 0; mt < 4; mt++) {
#pragma unroll
        for (int nt = 0; nt < 4; nt++) {
            int gm = m0 + wm + mt * 16 + qr;
            int gn = n0 + wn + nt * 8 + qc;
            float* d = acc[mt][nt];
            if (GEMM == 0) {
                float2 o0 = make_float2(silu_f(d[0]), silu_f(d[1]));
                float2 o1 = make_float2(silu_f(d[2]), silu_f(d[3]));
                *(float2*)(outp + (size_t)gm * LDC + gn) = o0;
                *(float2*)(outp + (size_t)(gm + 8) * LDC + gn) = o1;
            } else {
                float2 xa0 = *(const float2*)(x + (size_t)gm * DD + gn);
                float2 xa1 = *(const float2*)(x + (size_t)(gm + 8) * DD + gn);
                float2 rr  = *(const float2*)(res + gn);
                float2 o0 = make_float2(d[0] + xa0.x * rr.x, d[1] + xa0.y * rr.y);
                float2 o1 = make_float2(d[2] + xa1.x * rr.x, d[3] + xa1.y * rr.y);
                *(float2*)(outp + (size_t)gm * LDC + gn) = o0;
                *(float2*)(outp + (size_t)(gm + 8) * LDC + gn) = o1;
            }
        }
    }
}

// ---------------- attention v4: row-major v + ldmatrix.trans + bounce --------
// smem (bf16 elem offsets):
//   phase A: qh[144][136]@0 ql@19584 kh@39168 kl@58752
//   phase B: kernh[144][152]@0 kernl@21888
//            vth[144][136]@43776 vtl@63360  (end 82944 elem = 165888 B)
//   epilogue bounce: fp32 [144][132] overlaid on vth/vtl region (76032 B)
#define O_QH   0
#define O_QL   19584
#define O_KH   39168
#define O_KL   58752
#define O_KERH 0
#define O_KERL 21888
#define O_VTH  43776
#define O_VTL  63360
#define AT_SMEM_BYTES (82944 * 2)
#define SQK 136
#define SKR 152
#define SQKB 272
#define SKRB 304
#define SV   136
#define SVB  272

__global__ __launch_bounds__(576, 1)
void k_attn4(const float* __restrict__ gamma, const float* __restrict__ beta) {
    extern __shared__ __align__(16) __nv_bfloat16 sb[];
    uint32_t sbu = smem_u32(sb);
    int b = blockIdx.x, tid = threadIdx.x;
    int w = tid >> 5, lane = tid & 31;
    int w2 = w >> 1, half = w & 1;
    int qr = lane >> 2, qc = (lane & 3) * 2;
    int m = w2 * 16 + qr;
    const float* uvb = g_uv + (size_t)b * TT * NUV;

    // ldmatrix lane offsets (bytes)
    uint32_t aoffQ = (uint32_t)((w2 * 16 + (lane & 7) + ((lane >> 3) & 1) * 8) * SQKB
                                + ((lane >> 4) & 1) * 16);
    uint32_t boffQ = (uint32_t)((((lane >> 4) & 1) * 8 + (lane & 7)) * SQKB
                                + ((lane >> 3) & 1) * 16);
    uint32_t aoffR = (uint32_t)((w2 * 16 + (lane & 7) + ((lane >> 3) & 1) * 8) * SKRB
                                + ((lane >> 4) & 1) * 16);
    // trans-B for row-major v[k][n]: group g=lane/8: rows k0+(g&1)*8+r, cols n0+(g>>1)*8
    uint32_t boffV = (uint32_t)(((lane & 7) + ((lane >> 3) & 1) * 8) * SVB
                                + ((lane >> 4) & 1) * 16);

    // ---- phase A: build q/k hi-lo, rows >= TT zeroed ----
    for (int idx = tid; idx < 144 * 32; idx += 576) {
        int i = idx >> 5, s4 = (idx & 31) * 4;
        bool valid = (i < TT);
        float4 base = valid ? *(const float4*)(uvb + (size_t)i * NUV + 2*EE + s4)
                            : make_float4(0.f, 0.f, 0.f, 0.f);
        float4 ga = *(const float4*)(gamma + s4);
        float4 gk = *(const float4*)(gamma + SS + s4);
        float4 ba = *(const float4*)(beta + s4);
        float4 bk = *(const float4*)(beta + SS + s4);
        float q[4], k[4];
        q[0] = valid ? fmaf(base.x, ga.x, ba.x) : 0.f;
        q[1] = valid ? fmaf(base.y, ga.y, ba.y) : 0.f;
        q[2] = valid ? fmaf(base.z, ga.z, ba.z) : 0.f;
        q[3] = valid ? fmaf(base.w, ga.w, ba.w) : 0.f;
        k[0] = valid ? fmaf(base.x, gk.x, bk.x) : 0.f;
        k[1] = valid ? fmaf(base.y, gk.y, bk.y) : 0.f;
        k[2] = valid ? fmaf(base.z, gk.z, bk.z) : 0.f;
        k[3] = valid ? fmaf(base.w, gk.w, bk.w) : 0.f;
        __nv_bfloat16 qh[4], ql[4], kh[4], kl[4];
#pragma unroll
        for (int t = 0; t < 4; t++) { split1(q[t], qh[t], ql[t]); split1(k[t], kh[t], kl[t]); }
        int off = i * SQK + s4;
        *(__nv_bfloat162*)(sb + O_QH + off)     = __nv_bfloat162(qh[0], qh[1]);
        *(__nv_bfloat162*)(sb + O_QH + off + 2) = __nv_bfloat162(qh[2], qh[3]);
        *(__nv_bfloat162*)(sb + O_QL + off)     = __nv_bfloat162(ql[0], ql[1]);
        *(__nv_bfloat162*)(sb + O_QL + off + 2) = __nv_bfloat162(ql[2], ql[3]);
        *(__nv_bfloat162*)(sb + O_KH + off)     = __nv_bfloat162(kh[0], kh[1]);
        *(__nv_bfloat162*)(sb + O_KH + off + 2) = __nv_bfloat162(kh[2], kh[3]);
        *(__nv_bfloat162*)(sb + O_KL + off)     = __nv_bfloat162(kl[0], kl[1]);
        *(__nv_bfloat162*)(sb + O_KL + off + 2) = __nv_bfloat162(kl[2], kl[3]);
    }
    __syncthreads();

    // ---- scores (identical to validated round-9 path) ----
    const int np    = half ? 5 : 4;
    const int pbase = half ? 4 : 0;
    float acc[10][4];
#pragma unroll
    for (int i = 0; i < 10; i++)
#pragma unroll
        for (int t = 0; t < 4; t++) acc[i][t] = 0.f;

#pragma unroll
    for (int t = 0; t < 3; t++) {
        uint32_t Abase = sbu + ((t == 1) ? O_QL : O_QH) * 2;
        uint32_t Bbase = sbu + ((t == 2) ? O_KL : O_KH) * 2;
#pragma unroll
        for (int ks = 0; ks < 8; ks++) {
            uint32_t kof = ks * 32;
            uint32_t af[4];
            ldmx4(af, Abase + aoffQ + kof);
#pragma unroll
            for (int j = 0; j < 5; j++) {
                if (j < np) {
                    uint32_t bb[4];
                    ldmx4(bb, Bbase + boffQ + (uint32_t)(pbase + j) * 16 * SQKB + kof);
                    mma16816(acc[2*j],     af, bb[0], bb[1]);
                    mma16816(acc[2*j + 1], af, bb[2], bb[3]);
                }
            }
        }
    }
    __syncthreads();

    // ---- kern = relu(scores/sqrt(S))^2, split-store ----
#pragma unroll
    for (int j = 0; j < 5; j++) {
        if (j < np) {
#pragma unroll
            for (int s = 0; s < 2; s++) {
                int col = ((pbase + j) * 2 + s) * 8 + qc;
#pragma unroll
                for (int p = 0; p < 2; p++) {
                    int row = m + p * 8;
                    float v0 = fmaxf(acc[2*j + s][2*p]     * INV_SQRT_S, 0.f);
                    float v1 = fmaxf(acc[2*j + s][2*p + 1] * INV_SQRT_S, 0.f);
                    v0 *= v0; v1 *= v1;
                    __nv_bfloat16 h0, l0, h1, l1;
                    split1(v0, h0, l0); split1(v1, h1, l1);
                    *(__nv_bfloat162*)(sb + O_KERH + row * SKR + col) = __nv_bfloat162(h0, h1);
                    *(__nv_bfloat162*)(sb + O_KERL + row * SKR + col) = __nv_bfloat162(l0, l1);
                }
            }
        }
    }
    __syncthreads();

    // ---- attn chunks ----
    float* bounce = (float*)(sb + O_VTH);
    for (int ch = 0; ch < 4; ch++) {
        int e0 = ch * 128;
        // coalesced row-major fill of v hi/lo (conflict-free 8B stores)
        for (int idx = tid; idx < 144 * 32; idx += 576) {
            int j = idx >> 5, e4 = (idx & 31) * 4;
            float4 v = (j < TT) ? *(const float4*)(uvb + (size_t)j * NUV + EE + e0 + e4)
                                : make_float4(0.f, 0.f, 0.f, 0.f);
            __nv_bfloat16 h0,h1,h2,h3,l0,l1,l2,l3;
            split1(v.x,h0,l0); split1(v.y,h1,l1); split1(v.z,h2,l2); split1(v.w,h3,l3);
            int off = j * SV + e4;
            *(__nv_bfloat162*)(sb + O_VTH + off)     = __nv_bfloat162(h0, h1);
            *(__nv_bfloat162*)(sb + O_VTH + off + 2) = __nv_bfloat162(h2, h3);
            *(__nv_bfloat162*)(sb + O_VTL + off)     = __nv_bfloat162(l0, l1);
            *(__nv_bfloat162*)(sb + O_VTL + off + 2) = __nv_bfloat162(l2, l3);
        }
        __syncthreads();

        float acc2[8][4];
#pragma unroll
        for (int i = 0; i < 8; i++)
#pragma unroll
            for (int t = 0; t < 4; t++) acc2[i][t] = 0.f;

#pragma unroll
        for (int t = 0; t < 3; t++) {
            uint32_t Abase = sbu + ((t == 1) ? O_KERL : O_KERH) * 2;
            uint32_t Bbase = sbu + ((t == 2) ? O_VTL : O_VTH) * 2;
#pragma unroll
            for (int kt = 0; kt < 9; kt++) {
                uint32_t kof = (uint32_t)kt * 16 * SVB;
                uint32_t af[4];
                ldmx4(af, Abase + aoffR + (uint32_t)kt * 32);
#pragma unroll
                for (int j = 0; j < 4; j++) {
                    uint32_t bb[4];
                    ldmx4t(bb, Bbase + boffV + kof + (uint32_t)(4 * half + j) * 32);
                    mma16816(acc2[2*j],     af, bb[0], bb[1]);
                    mma16816(acc2[2*j + 1], af, bb[2], bb[3]);
                }
            }
        }
        __syncthreads();   // all mma reads of v done before bounce overwrite

        // bounce-write frags (fp32, stride 132)
#pragma unroll
        for (int j = 0; j < 4; j++) {
#pragma unroll
            for (int s = 0; s < 2; s++) {
                int colb = ((4 * half + j) * 2 + s) * 8 + qc;
#pragma unroll
                for (int p = 0; p < 2; p++) {
                    int row = m + p * 8;
                    *(float2*)(bounce + row * 132 + colb) =
                        make_float2(acc2[2*j + s][2*p], acc2[2*j + s][2*p + 1]);
                }
            }
        }
        __syncthreads();

        // coalesced epilogue: h = u * attn, split, 8B stores
        for (int idx = tid; idx < TT * 32; idx += 576) {
            int row = idx >> 5, c4 = (idx & 31) * 4;
            float4 a = *(const float4*)(bounce + row * 132 + c4);
            float4 u = *(const float4*)(uvb + (size_t)row * NUV + e0 + c4);
            float h0 = a.x * u.x, h1 = a.y * u.y, h2 = a.z * u.z, h3 = a.w * u.w;
            __nv_bfloat16 hh0,hl0,hh1,hl1,hh2,hl2,hh3,hl3;
            split1(h0,hh0,hl0); split1(h1,hh1,hl1);
            split1(h2,hh2,hl2); split1(h3,hh3,hl3);
            size_t ro = (size_t)(b * TT + row) * EE + e0 + c4;
            __nv_bfloat162* dh = (__nv_bfloat162*)(g_hh + ro);
            __nv_bfloat162* dl = (__nv_bfloat162*)(g_hl + ro);
            dh[0] = __nv_bfloat162(hh0, hh1); dh[1] = __nv_bfloat162(hh2, hh3);
            dl[0] = __nv_bfloat162(hl0, hl1); dl[1] = __nv_bfloat162(hl2, hl3);
        }
        __syncthreads();   // bounce reads done before next chunk's v fill
    }
}

// ---------------- launch ----------------------------------------------------
extern "C" void kernel_launch(void* const* d_in, const int* in_sizes, int n_in,
                              void* d_out, int out_size) {
    (void)in_sizes; (void)n_in; (void)out_size;
    const float* x     = (const float*)d_in[0];
    const float* W_uv  = (const float*)d_in[1];
    const float* W_o   = (const float*)d_in[2];
    const float* gamma = (const float*)d_in[3];
    const float* beta  = (const float*)d_in[4];
    const float* g     = (const float*)d_in[5];
    const float* res   = (const float*)d_in[6];
    float* out = (float*)d_out;

    cudaFuncSetAttribute(k_attn4, cudaFuncAttributeMaxDynamicSharedMemorySize,
                         AT_SMEM_BYTES);
    cudaFuncSetAttribute(k_gemm_mma<0>, cudaFuncAttributeMaxDynamicSharedMemorySize,
                         GM_SMEM);
    cudaFuncSetAttribute(k_gemm_mma<1>, cudaFuncAttributeMaxDynamicSharedMemorySize,
                         GM_SMEM);

    k_rnorm_split<<<MTOT / 8, dim3(32, 8)>>>(x, g);
    k_split_w<<<(NUV * 64 + DD * 128 + 255) / 256, 256>>>(W_uv, W_o);
    k_gemm_mma<0><<<dim3(NUV / 128, MTOT / 128), 256, GM_SMEM>>>(nullptr, nullptr, nullptr);
    k_attn4<<<BATCH, 576, AT_SMEM_BYTES>>>(gamma, beta);
    k_gemm_mma<1><<<dim3(DD / 128, MTOT / 128), 256, GM_SMEM>>>(x, res, out);
}